// round 8
// baseline (speedup 1.0000x reference)
#include <cuda_runtime.h>
#include <math.h>
#include <stdint.h>

#define BB 32
#define KPTS 2048
#define CFEAT 256
#define NPROP 256
#define NSAMP 16
#define NCOL 4096
#define K1P 288
#define OUTD 119
#define TOTROW (BB*NCOL)    // 131072
#define PROPROW (BB*NPROP)  // 8192

// single smem stage: Ah(4096) Al(4096) Bh(4096) Bl(4096) floats
#define STF 16384
#define GEMM_SMEM ((STF + 256) * 4)   // 66560 bytes

// ---------------- scratch ----------------
__device__ float d_featT[(size_t)BB*KPTS*CFEAT];
__device__ float d_xth[(size_t)TOTROW*K1P];
__device__ float d_xtl[(size_t)TOTROW*K1P];
__device__ float d_a1h[(size_t)TOTROW*CFEAT];
__device__ float d_a1l[(size_t)TOTROW*CFEAT];
__device__ float d_a2h[(size_t)TOTROW*CFEAT];
__device__ float d_a2l[(size_t)TOTROW*CFEAT];
__device__ float d_act3[(size_t)TOTROW*CFEAT];
__device__ float d_yh [(size_t)PROPROW*CFEAT];
__device__ float d_yl [(size_t)PROPROW*CFEAT];
__device__ float d_p1h[(size_t)PROPROW*CFEAT];
__device__ float d_p1l[(size_t)PROPROW*CFEAT];
__device__ float d_p2h[(size_t)PROPROW*CFEAT];
__device__ float d_p2l[(size_t)PROPROW*CFEAT];
__device__ float d_net[(size_t)PROPROW*128];
__device__ float d_newxyz[PROPROW*3];
__device__ int   d_idxbuf[PROPROW*NSAMP];
__device__ float d_sb[5*2*256];
__device__ float d_one[256];
__device__ float d_b3p[128];
__device__ float d_w1ph[2*9*4096],  d_w1pl[2*9*4096];
__device__ float d_w2ph[2*8*4096],  d_w2pl[2*8*4096];
__device__ float d_w3ph[2*8*4096],  d_w3pl[2*8*4096];
__device__ float d_pw1h[2*8*4096],  d_pw1l[2*8*4096];
__device__ float d_pw2h[2*8*4096],  d_pw2l[2*8*4096];
__device__ float d_hwh [1*8*4096],  d_hwl [1*8*4096];

// ---------------- output layout offsets ----------------
#define OFF_OBJ    0LL
#define OFF_CENTER 16384LL
#define OFF_SSC    40960LL
#define OFF_SRES   188416LL
#define OFF_PSIZE  630784LL
#define OFF_SEM    655360LL
#define OFF_CORN   802816LL
#define OFF_SLOG   999424LL
#define OFF_OPROB  1155072LL
#define OFF_SPROB  1163264LL

__device__ __forceinline__ uint32_t f2tf(float x) {
    uint32_t r; asm("cvt.rna.tf32.f32 %0, %1;" : "=r"(r) : "f"(x)); return r;
}
__device__ __forceinline__ uint32_t smem_u32(const void* p) {
    uint32_t a;
    asm("{ .reg .u64 t; cvta.to.shared.u64 t, %1; cvt.u32.u64 %0, t; }" : "=r"(a) : "l"(p));
    return a;
}
__device__ __forceinline__ void cp16(uint32_t s, const void* g) {
    asm volatile("cp.async.cg.shared.global [%0], [%1], 16;" :: "r"(s), "l"(g));
}
#define CP_COMMIT() asm volatile("cp.async.commit_group;" ::: "memory")
#define CP_WAIT0()  asm volatile("cp.async.wait_group 0;" ::: "memory")

__device__ __forceinline__ void mma_tf32(float* c, const uint32_t* a,
                                         uint32_t b0, uint32_t b1) {
    asm volatile(
        "mma.sync.aligned.m16n8k8.row.col.f32.tf32.tf32.f32 "
        "{%0,%1,%2,%3}, {%4,%5,%6,%7}, {%8,%9}, {%0,%1,%2,%3};"
        : "+f"(c[0]), "+f"(c[1]), "+f"(c[2]), "+f"(c[3])
        : "r"(a[0]), "r"(a[1]), "r"(a[2]), "r"(a[3]), "r"(b0), "r"(b1));
}

// A-side fragment-order offset for (row, col) given nkc K-chunks
__device__ __forceinline__ size_t afrag_off(int row, int c, int nkc) {
    return ((size_t)(row >> 4) * nkc + (c >> 5)) * 512
         + ((c >> 3) & 3) * 128
         + ((row & 7) * 4 + (c & 3)) * 4
         + ((row >> 3) & 1) + 2 * ((c >> 2) & 1);
}

// ============ 3xTF32 GEMM, fragment-ordered A & B, 2 CTAs/SM ============
__global__ __launch_bounds__(256, 2) void gemm_mma(
    const float* __restrict__ Ah, const float* __restrict__ Al, int nkcA,
    const float* __restrict__ Bph, const float* __restrict__ Bpl,
    float* __restrict__ Ch, float* __restrict__ Cl, int ldc,
    int nchunk,
    const float* __restrict__ scale, const float* __restrict__ bias, int mode)
{
    extern __shared__ float sm[];
    float* s_s = sm + STF;
    float* s_b = s_s + 128;
    const uint32_t smb = smem_u32(sm);

    const int tid = threadIdx.x;
    const int lane = tid & 31, wid = tid >> 5;
    const int wm = wid & 3, wn = wid >> 2;
    const long long m0 = (long long)blockIdx.x * 128;
    const long long m0b = (long long)blockIdx.x * 8;     // 16-row blocks
    const int yb = blockIdx.y, y0 = yb * 128;
    const int lq = lane >> 2, lr = lane & 3;

    if (tid < 128) {
        s_s[tid] = (mode == 0) ? scale[y0 + tid] : 1.0f;
        s_b[tid] = bias[y0 + tid];
    }

    float acc[2][8][4];
    #pragma unroll
    for (int mt = 0; mt < 2; mt++)
        #pragma unroll
        for (int nt = 0; nt < 8; nt++)
            #pragma unroll
            for (int j = 0; j < 4; j++) acc[mt][nt][j] = 0.0f;

    const long long bbase = (long long)yb * nchunk * 4096;

    for (int kc = 0; kc < nchunk; kc++) {
        // ---- stage (single buffer, cp.async) ----
        {
            #pragma unroll
            for (int it = 0; it < 4; it++) {
                int idx = tid + it * 256;               // 0..1023 uint4
                int bi = idx >> 7, off = (idx & 127) * 4;
                long long g = ((m0b + bi) * nkcA + kc) * 512 + off;
                uint32_t so = smb + (uint32_t)idx * 16;
                cp16(so, Ah + g);
                cp16(so + 4096*4, Al + g);
            }
            const long long bg = bbase + (long long)kc * 4096;
            #pragma unroll
            for (int it = 0; it < 4; it++) {
                int idx = tid + it * 256;
                uint32_t so = smb + 8192*4 + (uint32_t)idx * 16;
                cp16(so, Bph + bg + idx * 4);
                cp16(so + 4096*4, Bpl + bg + idx * 4);
            }
        }
        CP_COMMIT(); CP_WAIT0();
        __syncthreads();

        const float* sAh = sm;
        const float* sAl = sm + 4096;
        const float* sBh = sm + 8192;
        const float* sBl = sm + 12288;

        #pragma unroll
        for (int k8 = 0; k8 < 4; k8++) {
            uint4 ah0 = *(const uint4*)(sAh + (wm*2+0)*512 + k8*128 + lane*4);
            uint4 ah1 = *(const uint4*)(sAh + (wm*2+1)*512 + k8*128 + lane*4);
            uint4 al0 = *(const uint4*)(sAl + (wm*2+0)*512 + k8*128 + lane*4);
            uint4 al1 = *(const uint4*)(sAl + (wm*2+1)*512 + k8*128 + lane*4);
            uint2 bh[8], bl[8];
            #pragma unroll
            for (int nt = 0; nt < 8; nt++) {
                int fo = ((k8*16 + wn*8 + nt)*32 + lane) * 2;
                bh[nt] = *(const uint2*)(sBh + fo);
                bl[nt] = *(const uint2*)(sBl + fo);
            }
            #pragma unroll
            for (int nt = 0; nt < 8; nt++) {
                mma_tf32(acc[0][nt], (const uint32_t*)&al0, bh[nt].x, bh[nt].y);
                mma_tf32(acc[1][nt], (const uint32_t*)&al1, bh[nt].x, bh[nt].y);
            }
            #pragma unroll
            for (int nt = 0; nt < 8; nt++) {
                mma_tf32(acc[0][nt], (const uint32_t*)&ah0, bl[nt].x, bl[nt].y);
                mma_tf32(acc[1][nt], (const uint32_t*)&ah1, bl[nt].x, bl[nt].y);
            }
            #pragma unroll
            for (int nt = 0; nt < 8; nt++) {
                mma_tf32(acc[0][nt], (const uint32_t*)&ah0, bh[nt].x, bh[nt].y);
                mma_tf32(acc[1][nt], (const uint32_t*)&ah1, bh[nt].x, bh[nt].y);
            }
        }
        __syncthreads();
    }

    // ---- epilogue ----
    const int nkco = ldc >> 5;
    #pragma unroll
    for (int mt = 0; mt < 2; mt++) {
        long long r0 = m0 + wm * 32 + mt * 16 + lq;
        long long rb = (m0 + wm * 32 + mt * 16) >> 4;
        #pragma unroll
        for (int nt = 0; nt < 8; nt++) {
            int gc = wn * 64 + nt * 8 + 2 * lr;
            float s0 = s_s[gc], s1 = s_s[gc + 1];
            float b0 = s_b[gc], b1 = s_b[gc + 1];
            float v00 = acc[mt][nt][0] * s0 + b0;
            float v01 = acc[mt][nt][1] * s1 + b1;
            float v10 = acc[mt][nt][2] * s0 + b0;
            float v11 = acc[mt][nt][3] * s1 + b1;
            if (mode == 0) {
                v00 = fmaxf(v00, 0.f); v01 = fmaxf(v01, 0.f);
                v10 = fmaxf(v10, 0.f); v11 = fmaxf(v11, 0.f);
            }
            if (Cl) {
                // fragment-order hi/lo store for next layer (y0 folds into kc)
                int kc = (y0 >> 5) + wn * 2 + (nt >> 2);
                int k8 = nt & 3;
                long long blk = (rb * nkco + kc) * 512 + k8 * 128;
                int lane0 = lq * 4 + ((2*lr) & 3);
                int lane1 = lq * 4 + ((2*lr + 1) & 3);
                int chal2 = (lr >> 1) * 2;
                long long o00 = blk + lane0 * 4 + chal2;
                long long o01 = blk + lane1 * 4 + chal2;
                float h;
                h = __uint_as_float(f2tf(v00)); Ch[o00]   = h; Cl[o00]   = __uint_as_float(f2tf(v00 - h));
                h = __uint_as_float(f2tf(v01)); Ch[o01]   = h; Cl[o01]   = __uint_as_float(f2tf(v01 - h));
                h = __uint_as_float(f2tf(v10)); Ch[o00+1] = h; Cl[o00+1] = __uint_as_float(f2tf(v10 - h));
                h = __uint_as_float(f2tf(v11)); Ch[o01+1] = h; Cl[o01+1] = __uint_as_float(f2tf(v11 - h));
            } else {
                *(float2*)(Ch + r0 * ldc + y0 + gc)       = make_float2(v00, v01);
                *(float2*)(Ch + (r0 + 8) * ldc + y0 + gc) = make_float2(v10, v11);
            }
        }
    }
}

// ---------------- weight permute (per-k8 fragment order, hi/lo) ----------------
__global__ void permW_kernel(const float* __restrict__ W, int nrows, int ksrc,
                             int nkc, float* __restrict__ oh, float* __restrict__ ol) {
    int e = blockIdx.x * 256 + threadIdx.x;
    int yb = e / (nkc * 4096);
    int rem = e - yb * nkc * 4096;
    int kc = rem >> 12;
    int w = rem & 4095;
    int k8 = w >> 10, ntile = (w >> 6) & 15, lane = (w >> 1) & 31, j = w & 1;
    int o = yb * 128 + ntile * 8 + (lane >> 2);
    int k = kc * 32 + k8 * 8 + j * 4 + (lane & 3);
    float v = (o < nrows && k < ksrc) ? W[o * ksrc + k] : 0.0f;
    float h = __uint_as_float(f2tf(v));
    oh[e] = h;
    ol[e] = __uint_as_float(f2tf(v - h));
}

__global__ void sb_kernel(const float* __restrict__ sg, const float* __restrict__ sbe,
                          const float* __restrict__ sm, const float* __restrict__ sv,
                          const float* __restrict__ pg, const float* __restrict__ pb,
                          const float* __restrict__ pm, const float* __restrict__ pv,
                          const float* __restrict__ b3) {
    int l = blockIdx.x, t = threadIdx.x;
    if (l == 5) {
        if (t < 128) d_b3p[t] = (t < OUTD) ? b3[t] : 0.0f;
        d_one[t] = 1.0f;
        return;
    }
    float g, bt, m, v;
    if (l < 3) { g = sg[l*256+t]; bt = sbe[l*256+t]; m = sm[l*256+t]; v = sv[l*256+t]; }
    else { int q = l - 3; g = pg[q*256+t]; bt = pb[q*256+t]; m = pm[q*256+t]; v = pv[q*256+t]; }
    float s = g / sqrtf(v + 1e-5f);
    d_sb[l*512 + t] = s;
    d_sb[l*512 + 256 + t] = bt - m * s;
}

// ---------------- FPS ----------------
__global__ __launch_bounds__(256) void fps_kernel(const float* __restrict__ xyz) {
    __shared__ float sx[KPTS], sy[KPTS], sz[KPTS];
    __shared__ float wv_s[8];
    __shared__ int   wi_s[8];
    __shared__ int   sfar;
    int b = blockIdx.x, tid = threadIdx.x;
    const float* base = xyz + (size_t)b * KPTS * 3;
    for (int k = tid; k < KPTS; k += 256) {
        sx[k] = base[k*3+0]; sy[k] = base[k*3+1]; sz[k] = base[k*3+2];
    }
    float dreg[8];
    #pragma unroll
    for (int j = 0; j < 8; j++) dreg[j] = 1e10f;
    int far = 0;
    int warp = tid >> 5, lane = tid & 31;
    __syncthreads();
    for (int i = 0; i < NPROP; i++) {
        float cx = sx[far], cy = sy[far], cz = sz[far];
        if (tid == 0) {
            d_newxyz[(b*NPROP+i)*3+0] = cx;
            d_newxyz[(b*NPROP+i)*3+1] = cy;
            d_newxyz[(b*NPROP+i)*3+2] = cz;
        }
        float bv = -1.0f; int bi = 0x7fffffff;
        #pragma unroll
        for (int j = 0; j < 8; j++) {
            int k = tid + j * 256;
            float dx = sx[k]-cx, dy = sy[k]-cy, dz = sz[k]-cz;
            float d = __fadd_rn(__fadd_rn(__fmul_rn(dx,dx), __fmul_rn(dy,dy)), __fmul_rn(dz,dz));
            dreg[j] = fminf(dreg[j], d);
            if (dreg[j] > bv) { bv = dreg[j]; bi = k; }
        }
        unsigned bvb = __float_as_uint(bv);
        unsigned vmax = __reduce_max_sync(0xffffffffu, bvb);
        unsigned cand = (bvb == vmax) ? (unsigned)bi : 0x7fffffffu;
        unsigned bidx = __reduce_min_sync(0xffffffffu, cand);
        if (lane == 0) { wv_s[warp] = __uint_as_float(vmax); wi_s[warp] = (int)bidx; }
        __syncthreads();
        if (warp == 0) {
            unsigned v = (lane < 8) ? __float_as_uint(wv_s[lane]) : 0u;
            unsigned ii = (lane < 8) ? (unsigned)wi_s[lane] : 0x7fffffffu;
            unsigned vm = __reduce_max_sync(0xffffffffu, v);
            unsigned c2 = (v == vm) ? ii : 0x7fffffffu;
            unsigned idx = __reduce_min_sync(0xffffffffu, c2);
            if (lane == 0) sfar = (int)idx;
        }
        __syncthreads();
        far = sfar;
    }
}

// ---------------- ball query ----------------
__global__ __launch_bounds__(256) void bq_kernel(const float* __restrict__ xyz) {
    __shared__ float sx[KPTS], sy[KPTS], sz[KPTS];
    int b = blockIdx.x, tid = threadIdx.x;
    const float* base = xyz + (size_t)b * KPTS * 3;
    for (int k = tid; k < KPTS; k += 256) {
        sx[k] = base[k*3+0]; sy[k] = base[k*3+1]; sz[k] = base[k*3+2];
    }
    __syncthreads();
    int p = tid;
    float nx = d_newxyz[(b*NPROP+p)*3+0];
    float ny = d_newxyz[(b*NPROP+p)*3+1];
    float nz = d_newxyz[(b*NPROP+p)*3+2];
    int* dst = d_idxbuf + (b*NPROP+p)*NSAMP;
    int cnt = 0, first = 0;
    const float R2 = 0.09f;
    for (int k = 0; k < KPTS; k++) {
        float dx = sx[k]-nx, dy = sy[k]-ny, dz = sz[k]-nz;
        float d = __fadd_rn(__fadd_rn(__fmul_rn(dx,dx), __fmul_rn(dy,dy)), __fmul_rn(dz,dz));
        if (d < R2) {
            if (cnt == 0) first = k;
            dst[cnt] = k;
            if (++cnt == NSAMP) break;
        }
    }
    for (int j = cnt; j < NSAMP; j++) dst[j] = first;
}

// ---------------- feature transpose ----------------
__global__ void transpose_kernel(const float* __restrict__ in) {
    __shared__ float tile[32][33];
    int b = blockIdx.z;
    int k0 = blockIdx.x * 32, c0 = blockIdx.y * 32;
    const float* src = in + (size_t)b * CFEAT * KPTS;
    float* dst = d_featT + (size_t)b * KPTS * CFEAT;
    int tx = threadIdx.x, ty = threadIdx.y;
    #pragma unroll
    for (int i = 0; i < 4; i++)
        tile[ty + i*8][tx] = src[(size_t)(c0 + ty + i*8) * KPTS + k0 + tx];
    __syncthreads();
    #pragma unroll
    for (int i = 0; i < 4; i++)
        dst[(size_t)(k0 + ty + i*8) * CFEAT + c0 + tx] = tile[tx][ty + i*8];
}

// ---------------- gather: Xt hi/lo in fragment order ----------------
__global__ __launch_bounds__(128) void gather_kernel(const float* __restrict__ xyz) {
    int blk = blockIdx.x;
    int b = blk >> 8;
    int tid = threadIdx.x;
    __shared__ int   ks[NSAMP];
    __shared__ float cxyz[3];
    if (tid < NSAMP) ks[tid] = d_idxbuf[blk*NSAMP + tid];
    if (tid < 3)     cxyz[tid] = d_newxyz[blk*3 + tid];
    __syncthreads();
    for (int s = 0; s < NSAMP; s++) {
        int k = ks[s];
        const float* frow = d_featT + ((size_t)b * KPTS + k) * CFEAT;
        const float* prow = xyz + ((size_t)b * KPTS + k) * 3;
        int row = blk * NSAMP + s;
        for (int c = tid; c < K1P; c += 128) {
            float v;
            if (c < 3)        v = (prow[c] - cxyz[c]) / 0.3f;
            else if (c < 259) v = frow[c-3];
            else              v = 0.0f;
            size_t o = afrag_off(row, c, 9);
            float h = __uint_as_float(f2tf(v));
            d_xth[o] = h;
            d_xtl[o] = __uint_as_float(f2tf(v - h));
        }
    }
}

// ---------------- maxpool: act3 -> Y hi/lo (fragment order) ----------------
__global__ __launch_bounds__(256) void maxpool_kernel() {
    int blk = blockIdx.x;
    int c = threadIdx.x;
    const float* src = d_act3 + (size_t)blk * NSAMP * CFEAT;
    float m = src[c];
    #pragma unroll
    for (int s = 1; s < NSAMP; s++) m = fmaxf(m, src[s*CFEAT + c]);
    size_t o = afrag_off(blk, c, 8);
    float h = __uint_as_float(f2tf(m));
    d_yh[o] = h;
    d_yl[o] = __uint_as_float(f2tf(m - h));
}

// ---------------- decode head ----------------
__global__ __launch_bounds__(256) void decode_kernel(const float* __restrict__ msa,
                                                     float* __restrict__ out) {
    int g = blockIdx.x * 256 + threadIdx.x;
    if (g >= PROPROW) return;
    const float* nt = d_net + (size_t)g * 128;
    const float* nx = d_newxyz + (size_t)g * 3;

    float obj0 = nt[0], obj1 = nt[1];
    out[OFF_OBJ + 2*g + 0] = obj0;
    out[OFF_OBJ + 2*g + 1] = obj1;

    float cen[3];
    #pragma unroll
    for (int c = 0; c < 3; c++) {
        cen[c] = nx[c] + nt[2 + c];
        out[OFF_CENTER + 3*g + c] = cen[c];
    }

    float bestv = -1e30f; int best = 0;
    #pragma unroll
    for (int j = 0; j < 18; j++) {
        float s = nt[29 + j];
        out[OFF_SSC + 18*g + j] = s;
        if (s > bestv) { bestv = s; best = j; }
    }

    #pragma unroll
    for (int j = 0; j < 18; j++)
        #pragma unroll
        for (int c = 0; c < 3; c++)
            out[OFF_SRES + 54*g + j*3 + c] = nt[47 + j*3 + c] * msa[j*3 + c];

    float ps[3];
    #pragma unroll
    for (int c = 0; c < 3; c++) {
        ps[c] = nt[47 + best*3 + c] * msa[best*3 + c] + msa[best*3 + c];
        out[OFF_PSIZE + 3*g + c] = ps[c];
    }

    float mx = -1e30f;
    #pragma unroll
    for (int j = 0; j < 18; j++) {
        float s = nt[101 + j];
        out[OFF_SEM  + 18*g + j] = s;
        out[OFF_SLOG + 19*g + j] = s;
        mx = fmaxf(mx, s);
    }
    float e[18], sum = 0.0f;
    #pragma unroll
    for (int j = 0; j < 18; j++) { e[j] = expf(nt[101 + j] - mx); sum += e[j]; }
    #pragma unroll
    for (int j = 0; j < 18; j++) out[OFF_SPROB + 18*g + j] = e[j] / sum;

    out[OFF_SLOG + 19*g + 18] = (obj0 <= obj1) ? 0.0f : 1e10f;

    float m2 = fmaxf(obj0, obj1);
    float e0 = expf(obj0 - m2), e1 = expf(obj1 - m2);
    out[OFF_OPROB + g] = e1 / (e0 + e1);

    float cc0 = cen[0], cc1 = cen[2], cc2 = -cen[1];
    const float sxv[8] = {1,1,-1,-1,1,1,-1,-1};
    const float syv[8] = {1,1,1,1,-1,-1,-1,-1};
    const float szv[8] = {1,-1,-1,1,1,-1,-1,1};
    #pragma unroll
    for (int k = 0; k < 8; k++) {
        out[OFF_CORN + 24*g + k*3 + 0] = cc0 + ps[0] * sxv[k] * 0.5f;
        out[OFF_CORN + 24*g + k*3 + 1] = cc1 + ps[2] * syv[k] * 0.5f;
        out[OFF_CORN + 24*g + k*3 + 2] = cc2 + ps[1] * szv[k] * 0.5f;
    }
}

// ---------------- launch ----------------
extern "C" void kernel_launch(void* const* d_in, const int* in_sizes, int n_in,
                              void* d_out, int out_size) {
    const float* xyz      = (const float*)d_in[0];
    const float* features = (const float*)d_in[1];
    const float* sa_w1    = (const float*)d_in[2];
    const float* sa_w2    = (const float*)d_in[3];
    const float* sa_w3    = (const float*)d_in[4];
    const float* sa_gamma = (const float*)d_in[5];
    const float* sa_beta  = (const float*)d_in[6];
    const float* sa_mean  = (const float*)d_in[7];
    const float* sa_var   = (const float*)d_in[8];
    const float* p_w1     = (const float*)d_in[9];
    const float* p_w2     = (const float*)d_in[10];
    const float* p_w3     = (const float*)d_in[11];
    const float* p_b3     = (const float*)d_in[12];
    const float* p_gamma  = (const float*)d_in[13];
    const float* p_beta   = (const float*)d_in[14];
    const float* p_mean   = (const float*)d_in[15];
    const float* p_var    = (const float*)d_in[16];
    const float* msa      = (const float*)d_in[17];
    float* out = (float*)d_out;

    #define GA(sym) ({ void* _p; cudaGetSymbolAddress(&_p, sym); (float*)_p; })
    float* XTH = GA(d_xth); float* XTL = GA(d_xtl);
    float* A1H = GA(d_a1h); float* A1L = GA(d_a1l);
    float* A2H = GA(d_a2h); float* A2L = GA(d_a2l);
    float* A3  = GA(d_act3);
    float* YH  = GA(d_yh);  float* YL  = GA(d_yl);
    float* P1H = GA(d_p1h); float* P1L = GA(d_p1l);
    float* P2H = GA(d_p2h); float* P2L = GA(d_p2l);
    float* NET = GA(d_net);
    float* SB  = GA(d_sb);  float* ONE = GA(d_one); float* B3P = GA(d_b3p);
    float* W1H = GA(d_w1ph); float* W1L = GA(d_w1pl);
    float* W2H = GA(d_w2ph); float* W2L = GA(d_w2pl);
    float* W3H = GA(d_w3ph); float* W3L = GA(d_w3pl);
    float* Q1H = GA(d_pw1h); float* Q1L = GA(d_pw1l);
    float* Q2H = GA(d_pw2h); float* Q2L = GA(d_pw2l);
    float* HWH = GA(d_hwh);  float* HWL = GA(d_hwl);
    #undef GA

    cudaFuncSetAttribute(gemm_mma, cudaFuncAttributeMaxDynamicSharedMemorySize, GEMM_SMEM);

    permW_kernel<<<2*9*16, 256>>>(sa_w1, 256, 259, 9, W1H, W1L);
    permW_kernel<<<2*8*16, 256>>>(sa_w2, 256, 256, 8, W2H, W2L);
    permW_kernel<<<2*8*16, 256>>>(sa_w3, 256, 256, 8, W3H, W3L);
    permW_kernel<<<2*8*16, 256>>>(p_w1, 256, 256, 8, Q1H, Q1L);
    permW_kernel<<<2*8*16, 256>>>(p_w2, 256, 256, 8, Q2H, Q2L);
    permW_kernel<<<1*8*16, 256>>>(p_w3, OUTD, 256, 8, HWH, HWL);
    sb_kernel<<<6, 256>>>(sa_gamma, sa_beta, sa_mean, sa_var,
                          p_gamma, p_beta, p_mean, p_var, p_b3);
    fps_kernel<<<BB, 256>>>(xyz);
    bq_kernel<<<BB, 256>>>(xyz);
    transpose_kernel<<<dim3(KPTS/32, CFEAT/32, BB), dim3(32, 8)>>>(features);
    gather_kernel<<<PROPROW, 128>>>(xyz);

    // SA layers
    gemm_mma<<<dim3(TOTROW/128, 2), 256, GEMM_SMEM>>>(XTH, XTL, 9, W1H, W1L,
        A1H, A1L, 256, 9, SB + 0*512, SB + 0*512 + 256, 0);
    gemm_mma<<<dim3(TOTROW/128, 2), 256, GEMM_SMEM>>>(A1H, A1L, 8, W2H, W2L,
        A2H, A2L, 256, 8, SB + 1*512, SB + 1*512 + 256, 0);
    gemm_mma<<<dim3(TOTROW/128, 2), 256, GEMM_SMEM>>>(A2H, A2L, 8, W3H, W3L,
        A3, (float*)0, 256, 8, SB + 2*512, SB + 2*512 + 256, 0);

    maxpool_kernel<<<PROPROW, 256>>>();

    // proposal layers
    gemm_mma<<<dim3(PROPROW/128, 2), 256, GEMM_SMEM>>>(YH, YL, 8, Q1H, Q1L,
        P1H, P1L, 256, 8, SB + 3*512, SB + 3*512 + 256, 0);
    gemm_mma<<<dim3(PROPROW/128, 2), 256, GEMM_SMEM>>>(P1H, P1L, 8, Q2H, Q2L,
        P2H, P2L, 256, 8, SB + 4*512, SB + 4*512 + 256, 0);
    gemm_mma<<<dim3(PROPROW/128, 1), 256, GEMM_SMEM>>>(P2H, P2L, 8, HWH, HWL,
        NET, (float*)0, 128, 8, ONE, B3P, 1);

    decode_kernel<<<PROPROW/256, 256>>>(msa, out);
}

// round 9
// speedup vs baseline: 1.0147x; 1.0147x over previous
#include <cuda_runtime.h>
#include <math.h>
#include <stdint.h>

#define BB 32
#define KPTS 2048
#define CFEAT 256
#define NPROP 256
#define NSAMP 16
#define NCOL 4096
#define K1P 288
#define OUTD 119
#define TOTROW (BB*NCOL)    // 131072
#define PROPROW (BB*NPROP)  // 8192

// B-only smem stage: Bh(4096)+Bl(4096) floats = 32KB; 2 stages
#define BSTF 8192
#define GEMM_SMEM ((2*BSTF + 256) * 4)   // 66560 bytes -> 2 CTAs/SM

// ---------------- scratch ----------------
__device__ float d_featT[(size_t)BB*KPTS*CFEAT];
__device__ float d_xth[(size_t)TOTROW*K1P];
__device__ float d_xtl[(size_t)TOTROW*K1P];
__device__ float d_a1h[(size_t)TOTROW*CFEAT];
__device__ float d_a1l[(size_t)TOTROW*CFEAT];
__device__ float d_a2h[(size_t)TOTROW*CFEAT];
__device__ float d_a2l[(size_t)TOTROW*CFEAT];
__device__ float d_act3[(size_t)TOTROW*CFEAT];
__device__ float d_yh [(size_t)PROPROW*CFEAT];
__device__ float d_yl [(size_t)PROPROW*CFEAT];
__device__ float d_p1h[(size_t)PROPROW*CFEAT];
__device__ float d_p1l[(size_t)PROPROW*CFEAT];
__device__ float d_p2h[(size_t)PROPROW*CFEAT];
__device__ float d_p2l[(size_t)PROPROW*CFEAT];
__device__ float d_net[(size_t)PROPROW*128];
__device__ float d_newxyz[PROPROW*3];
__device__ int   d_idxbuf[PROPROW*NSAMP];
__device__ float d_sb[5*2*256];
__device__ float d_one[256];
__device__ float d_b3p[128];
__device__ float d_w1ph[2*9*4096],  d_w1pl[2*9*4096];
__device__ float d_w2ph[2*8*4096],  d_w2pl[2*8*4096];
__device__ float d_w3ph[2*8*4096],  d_w3pl[2*8*4096];
__device__ float d_pw1h[2*8*4096],  d_pw1l[2*8*4096];
__device__ float d_pw2h[2*8*4096],  d_pw2l[2*8*4096];
__device__ float d_hwh [1*8*4096],  d_hwl [1*8*4096];

// ---------------- output layout offsets ----------------
#define OFF_OBJ    0LL
#define OFF_CENTER 16384LL
#define OFF_SSC    40960LL
#define OFF_SRES   188416LL
#define OFF_PSIZE  630784LL
#define OFF_SEM    655360LL
#define OFF_CORN   802816LL
#define OFF_SLOG   999424LL
#define OFF_OPROB  1155072LL
#define OFF_SPROB  1163264LL

__device__ __forceinline__ uint32_t f2tf(float x) {
    uint32_t r; asm("cvt.rna.tf32.f32 %0, %1;" : "=r"(r) : "f"(x)); return r;
}
__device__ __forceinline__ uint32_t smem_u32(const void* p) {
    uint32_t a;
    asm("{ .reg .u64 t; cvta.to.shared.u64 t, %1; cvt.u32.u64 %0, t; }" : "=r"(a) : "l"(p));
    return a;
}
__device__ __forceinline__ void cp16(uint32_t s, const void* g) {
    asm volatile("cp.async.cg.shared.global [%0], [%1], 16;" :: "r"(s), "l"(g));
}
#define CP_COMMIT() asm volatile("cp.async.commit_group;" ::: "memory")
#define CP_WAIT1()  asm volatile("cp.async.wait_group 1;" ::: "memory")
#define CP_WAIT0()  asm volatile("cp.async.wait_group 0;" ::: "memory")

__device__ __forceinline__ void mma_tf32(float* c, const uint32_t* a,
                                         uint32_t b0, uint32_t b1) {
    asm volatile(
        "mma.sync.aligned.m16n8k8.row.col.f32.tf32.tf32.f32 "
        "{%0,%1,%2,%3}, {%4,%5,%6,%7}, {%8,%9}, {%0,%1,%2,%3};"
        : "+f"(c[0]), "+f"(c[1]), "+f"(c[2]), "+f"(c[3])
        : "r"(a[0]), "r"(a[1]), "r"(a[2]), "r"(a[3]), "r"(b0), "r"(b1));
}

// A-side fragment-order offset for (row, col) given nkc K-chunks
__device__ __forceinline__ size_t afrag_off(int row, int c, int nkc) {
    return ((size_t)(row >> 4) * nkc + (c >> 5)) * 512
         + ((c >> 3) & 3) * 128
         + ((row & 7) * 4 + (c & 3)) * 4
         + ((row >> 3) & 1) + 2 * ((c >> 2) & 1);
}

// ============ 3xTF32 GEMM: B smem double-buffered, A direct LDG ============
// 1D grid, yb in low bits (nybm1 = nyb-1, 0 or 1) for L2 reuse of A.
__global__ __launch_bounds__(256, 2) void gemm_mma(
    const float* __restrict__ Ah, const float* __restrict__ Al, int nkcA,
    const float* __restrict__ Bph, const float* __restrict__ Bpl,
    float* __restrict__ Ch, float* __restrict__ Cl, int ldc,
    int nchunk,
    const float* __restrict__ scale, const float* __restrict__ bias,
    int mode, int nybm1)
{
    extern __shared__ float sm[];
    float* s_s = sm + 2*BSTF;
    float* s_b = s_s + 128;
    const uint32_t smb = smem_u32(sm);

    const int tid = threadIdx.x;
    const int lane = tid & 31, wid = tid >> 5;
    const int wm = wid & 3, wn = wid >> 2;
    const int yb = blockIdx.x & nybm1;
    const long long xb = blockIdx.x >> nybm1;
    const long long m0 = xb * 128;
    const int y0 = yb * 128;
    const int lq = lane >> 2, lr = lane & 3;

    if (tid < 128) {
        s_s[tid] = (mode == 0) ? scale[y0 + tid] : 1.0f;
        s_b[tid] = bias[y0 + tid];
    }

    float acc[2][8][4];
    #pragma unroll
    for (int mt = 0; mt < 2; mt++)
        #pragma unroll
        for (int nt = 0; nt < 8; nt++)
            #pragma unroll
            for (int j = 0; j < 4; j++) acc[mt][nt][j] = 0.0f;

    // per-warp A fragment streams (row-blocks xb*8 + wm*2 + mt)
    const size_t rb0 = (size_t)(xb * 8 + wm * 2 + 0) * nkcA * 512 + lane * 4;
    const size_t rb1 = (size_t)(xb * 8 + wm * 2 + 1) * nkcA * 512 + lane * 4;
    const float* pAh0 = Ah + rb0;  const float* pAh1 = Ah + rb1;
    const float* pAl0 = Al + rb0;  const float* pAl1 = Al + rb1;

    const long long bbase = (long long)yb * nchunk * 4096;

    // B stage loader: 8 cp16 per thread
    auto stageB = [&](int kc) {
        const uint32_t sb0 = smb + (kc & 1) * BSTF * 4;
        const long long bg = bbase + (long long)kc * 4096;
        #pragma unroll
        for (int it = 0; it < 4; it++) {
            int idx = tid + it * 256;                 // 0..1023 uint4
            cp16(sb0 + (uint32_t)idx * 16, Bph + bg + idx * 4);
            cp16(sb0 + 4096*4 + (uint32_t)idx * 16, Bpl + bg + idx * 4);
        }
    };

    stageB(0); CP_COMMIT();

    for (int kc = 0; kc < nchunk; kc++) {
        if (kc + 1 < nchunk) { stageB(kc + 1); CP_COMMIT(); CP_WAIT1(); }
        else CP_WAIT0();
        __syncthreads();

        const float* sBh = sm + (kc & 1) * BSTF;
        const float* sBl = sBh + 4096;
        const int cb = kc * 512;

        #pragma unroll
        for (int k8 = 0; k8 < 4; k8++) {
            const int ao = cb + k8 * 128;
            uint4 ah0 = *(const uint4*)(pAh0 + ao);
            uint4 ah1 = *(const uint4*)(pAh1 + ao);
            uint4 al0 = *(const uint4*)(pAl0 + ao);
            uint4 al1 = *(const uint4*)(pAl1 + ao);
            uint2 bh[8], bl[8];
            #pragma unroll
            for (int nt = 0; nt < 8; nt++) {
                int fo = ((k8*16 + wn*8 + nt)*32 + lane) * 2;
                bh[nt] = *(const uint2*)(sBh + fo);
                bl[nt] = *(const uint2*)(sBl + fo);
            }
            #pragma unroll
            for (int nt = 0; nt < 8; nt++) {
                mma_tf32(acc[0][nt], (const uint32_t*)&al0, bh[nt].x, bh[nt].y);
                mma_tf32(acc[1][nt], (const uint32_t*)&al1, bh[nt].x, bh[nt].y);
            }
            #pragma unroll
            for (int nt = 0; nt < 8; nt++) {
                mma_tf32(acc[0][nt], (const uint32_t*)&ah0, bl[nt].x, bl[nt].y);
                mma_tf32(acc[1][nt], (const uint32_t*)&ah1, bl[nt].x, bl[nt].y);
            }
            #pragma unroll
            for (int nt = 0; nt < 8; nt++) {
                mma_tf32(acc[0][nt], (const uint32_t*)&ah0, bh[nt].x, bh[nt].y);
                mma_tf32(acc[1][nt], (const uint32_t*)&ah1, bh[nt].x, bh[nt].y);
            }
        }
        __syncthreads();
    }

    // ---- epilogue ----
    const int nkco = ldc >> 5;
    #pragma unroll
    for (int mt = 0; mt < 2; mt++) {
        long long r0 = m0 + wm * 32 + mt * 16 + lq;
        long long rb = (m0 + wm * 32 + mt * 16) >> 4;
        #pragma unroll
        for (int nt = 0; nt < 8; nt++) {
            int gc = wn * 64 + nt * 8 + 2 * lr;
            float s0 = s_s[gc], s1 = s_s[gc + 1];
            float b0 = s_b[gc], b1 = s_b[gc + 1];
            float v00 = acc[mt][nt][0] * s0 + b0;
            float v01 = acc[mt][nt][1] * s1 + b1;
            float v10 = acc[mt][nt][2] * s0 + b0;
            float v11 = acc[mt][nt][3] * s1 + b1;
            if (mode == 0) {
                v00 = fmaxf(v00, 0.f); v01 = fmaxf(v01, 0.f);
                v10 = fmaxf(v10, 0.f); v11 = fmaxf(v11, 0.f);
            }
            if (Cl) {
                int kc = (y0 >> 5) + wn * 2 + (nt >> 2);
                int k8 = nt & 3;
                long long blk = (rb * nkco + kc) * 512 + k8 * 128;
                int lane0 = lq * 4 + ((2*lr) & 3);
                int lane1 = lq * 4 + ((2*lr + 1) & 3);
                int chal2 = (lr >> 1) * 2;
                long long o00 = blk + lane0 * 4 + chal2;
                long long o01 = blk + lane1 * 4 + chal2;
                float h;
                h = __uint_as_float(f2tf(v00)); Ch[o00]   = h; Cl[o00]   = __uint_as_float(f2tf(v00 - h));
                h = __uint_as_float(f2tf(v01)); Ch[o01]   = h; Cl[o01]   = __uint_as_float(f2tf(v01 - h));
                h = __uint_as_float(f2tf(v10)); Ch[o00+1] = h; Cl[o00+1] = __uint_as_float(f2tf(v10 - h));
                h = __uint_as_float(f2tf(v11)); Ch[o01+1] = h; Cl[o01+1] = __uint_as_float(f2tf(v11 - h));
            } else {
                *(float2*)(Ch + r0 * ldc + y0 + gc)       = make_float2(v00, v01);
                *(float2*)(Ch + (r0 + 8) * ldc + y0 + gc) = make_float2(v10, v11);
            }
        }
    }
}

// ---------------- weight permute (per-k8 fragment order, hi/lo) ----------------
__global__ void permW_kernel(const float* __restrict__ W, int nrows, int ksrc,
                             int nkc, float* __restrict__ oh, float* __restrict__ ol) {
    int e = blockIdx.x * 256 + threadIdx.x;
    int yb = e / (nkc * 4096);
    int rem = e - yb * nkc * 4096;
    int kc = rem >> 12;
    int w = rem & 4095;
    int k8 = w >> 10, ntile = (w >> 6) & 15, lane = (w >> 1) & 31, j = w & 1;
    int o = yb * 128 + ntile * 8 + (lane >> 2);
    int k = kc * 32 + k8 * 8 + j * 4 + (lane & 3);
    float v = (o < nrows && k < ksrc) ? W[o * ksrc + k] : 0.0f;
    float h = __uint_as_float(f2tf(v));
    oh[e] = h;
    ol[e] = __uint_as_float(f2tf(v - h));
}

__global__ void sb_kernel(const float* __restrict__ sg, const float* __restrict__ sbe,
                          const float* __restrict__ sm, const float* __restrict__ sv,
                          const float* __restrict__ pg, const float* __restrict__ pb,
                          const float* __restrict__ pm, const float* __restrict__ pv,
                          const float* __restrict__ b3) {
    int l = blockIdx.x, t = threadIdx.x;
    if (l == 5) {
        if (t < 128) d_b3p[t] = (t < OUTD) ? b3[t] : 0.0f;
        d_one[t] = 1.0f;
        return;
    }
    float g, bt, m, v;
    if (l < 3) { g = sg[l*256+t]; bt = sbe[l*256+t]; m = sm[l*256+t]; v = sv[l*256+t]; }
    else { int q = l - 3; g = pg[q*256+t]; bt = pb[q*256+t]; m = pm[q*256+t]; v = pv[q*256+t]; }
    float s = g / sqrtf(v + 1e-5f);
    d_sb[l*512 + t] = s;
    d_sb[l*512 + 256 + t] = bt - m * s;
}

// ---------------- FPS ----------------
__global__ __launch_bounds__(256) void fps_kernel(const float* __restrict__ xyz) {
    __shared__ float sx[KPTS], sy[KPTS], sz[KPTS];
    __shared__ float wv_s[8];
    __shared__ int   wi_s[8];
    __shared__ int   sfar;
    int b = blockIdx.x, tid = threadIdx.x;
    const float* base = xyz + (size_t)b * KPTS * 3;
    for (int k = tid; k < KPTS; k += 256) {
        sx[k] = base[k*3+0]; sy[k] = base[k*3+1]; sz[k] = base[k*3+2];
    }
    float dreg[8];
    #pragma unroll
    for (int j = 0; j < 8; j++) dreg[j] = 1e10f;
    int far = 0;
    int warp = tid >> 5, lane = tid & 31;
    __syncthreads();
    for (int i = 0; i < NPROP; i++) {
        float cx = sx[far], cy = sy[far], cz = sz[far];
        if (tid == 0) {
            d_newxyz[(b*NPROP+i)*3+0] = cx;
            d_newxyz[(b*NPROP+i)*3+1] = cy;
            d_newxyz[(b*NPROP+i)*3+2] = cz;
        }
        float bv = -1.0f; int bi = 0x7fffffff;
        #pragma unroll
        for (int j = 0; j < 8; j++) {
            int k = tid + j * 256;
            float dx = sx[k]-cx, dy = sy[k]-cy, dz = sz[k]-cz;
            float d = __fadd_rn(__fadd_rn(__fmul_rn(dx,dx), __fmul_rn(dy,dy)), __fmul_rn(dz,dz));
            dreg[j] = fminf(dreg[j], d);
            if (dreg[j] > bv) { bv = dreg[j]; bi = k; }
        }
        unsigned bvb = __float_as_uint(bv);
        unsigned vmax = __reduce_max_sync(0xffffffffu, bvb);
        unsigned cand = (bvb == vmax) ? (unsigned)bi : 0x7fffffffu;
        unsigned bidx = __reduce_min_sync(0xffffffffu, cand);
        if (lane == 0) { wv_s[warp] = __uint_as_float(vmax); wi_s[warp] = (int)bidx; }
        __syncthreads();
        if (warp == 0) {
            unsigned v = (lane < 8) ? __float_as_uint(wv_s[lane]) : 0u;
            unsigned ii = (lane < 8) ? (unsigned)wi_s[lane] : 0x7fffffffu;
            unsigned vm = __reduce_max_sync(0xffffffffu, v);
            unsigned c2 = (v == vm) ? ii : 0x7fffffffu;
            unsigned idx = __reduce_min_sync(0xffffffffu, c2);
            if (lane == 0) sfar = (int)idx;
        }
        __syncthreads();
        far = sfar;
    }
}

// ---------------- ball query ----------------
__global__ __launch_bounds__(256) void bq_kernel(const float* __restrict__ xyz) {
    __shared__ float sx[KPTS], sy[KPTS], sz[KPTS];
    int b = blockIdx.x, tid = threadIdx.x;
    const float* base = xyz + (size_t)b * KPTS * 3;
    for (int k = tid; k < KPTS; k += 256) {
        sx[k] = base[k*3+0]; sy[k] = base[k*3+1]; sz[k] = base[k*3+2];
    }
    __syncthreads();
    int p = tid;
    float nx = d_newxyz[(b*NPROP+p)*3+0];
    float ny = d_newxyz[(b*NPROP+p)*3+1];
    float nz = d_newxyz[(b*NPROP+p)*3+2];
    int* dst = d_idxbuf + (b*NPROP+p)*NSAMP;
    int cnt = 0, first = 0;
    const float R2 = 0.09f;
    for (int k = 0; k < KPTS; k++) {
        float dx = sx[k]-nx, dy = sy[k]-ny, dz = sz[k]-nz;
        float d = __fadd_rn(__fadd_rn(__fmul_rn(dx,dx), __fmul_rn(dy,dy)), __fmul_rn(dz,dz));
        if (d < R2) {
            if (cnt == 0) first = k;
            dst[cnt] = k;
            if (++cnt == NSAMP) break;
        }
    }
    for (int j = cnt; j < NSAMP; j++) dst[j] = first;
}

// ---------------- feature transpose ----------------
__global__ void transpose_kernel(const float* __restrict__ in) {
    __shared__ float tile[32][33];
    int b = blockIdx.z;
    int k0 = blockIdx.x * 32, c0 = blockIdx.y * 32;
    const float* src = in + (size_t)b * CFEAT * KPTS;
    float* dst = d_featT + (size_t)b * KPTS * CFEAT;
    int tx = threadIdx.x, ty = threadIdx.y;
    #pragma unroll
    for (int i = 0; i < 4; i++)
        tile[ty + i*8][tx] = src[(size_t)(c0 + ty + i*8) * KPTS + k0 + tx];
    __syncthreads();
    #pragma unroll
    for (int i = 0; i < 4; i++)
        dst[(size_t)(k0 + ty + i*8) * CFEAT + c0 + tx] = tile[tx][ty + i*8];
}

// ---------------- gather: Xt hi/lo in fragment order ----------------
__global__ __launch_bounds__(128) void gather_kernel(const float* __restrict__ xyz) {
    int blk = blockIdx.x;
    int b = blk >> 8;
    int tid = threadIdx.x;
    __shared__ int   ks[NSAMP];
    __shared__ float cxyz[3];
    if (tid < NSAMP) ks[tid] = d_idxbuf[blk*NSAMP + tid];
    if (tid < 3)     cxyz[tid] = d_newxyz[blk*3 + tid];
    __syncthreads();
    for (int s = 0; s < NSAMP; s++) {
        int k = ks[s];
        const float* frow = d_featT + ((size_t)b * KPTS + k) * CFEAT;
        const float* prow = xyz + ((size_t)b * KPTS + k) * 3;
        int row = blk * NSAMP + s;
        for (int c = tid; c < K1P; c += 128) {
            float v;
            if (c < 3)        v = (prow[c] - cxyz[c]) / 0.3f;
            else if (c < 259) v = frow[c-3];
            else              v = 0.0f;
            size_t o = afrag_off(row, c, 9);
            float h = __uint_as_float(f2tf(v));
            d_xth[o] = h;
            d_xtl[o] = __uint_as_float(f2tf(v - h));
        }
    }
}

// ---------------- maxpool: act3 -> Y hi/lo (fragment order) ----------------
__global__ __launch_bounds__(256) void maxpool_kernel() {
    int blk = blockIdx.x;
    int c = threadIdx.x;
    const float* src = d_act3 + (size_t)blk * NSAMP * CFEAT;
    float m = src[c];
    #pragma unroll
    for (int s = 1; s < NSAMP; s++) m = fmaxf(m, src[s*CFEAT + c]);
    size_t o = afrag_off(blk, c, 8);
    float h = __uint_as_float(f2tf(m));
    d_yh[o] = h;
    d_yl[o] = __uint_as_float(f2tf(m - h));
}

// ---------------- decode head ----------------
__global__ __launch_bounds__(256) void decode_kernel(const float* __restrict__ msa,
                                                     float* __restrict__ out) {
    int g = blockIdx.x * 256 + threadIdx.x;
    if (g >= PROPROW) return;
    const float* nt = d_net + (size_t)g * 128;
    const float* nx = d_newxyz + (size_t)g * 3;

    float obj0 = nt[0], obj1 = nt[1];
    out[OFF_OBJ + 2*g + 0] = obj0;
    out[OFF_OBJ + 2*g + 1] = obj1;

    float cen[3];
    #pragma unroll
    for (int c = 0; c < 3; c++) {
        cen[c] = nx[c] + nt[2 + c];
        out[OFF_CENTER + 3*g + c] = cen[c];
    }

    float bestv = -1e30f; int best = 0;
    #pragma unroll
    for (int j = 0; j < 18; j++) {
        float s = nt[29 + j];
        out[OFF_SSC + 18*g + j] = s;
        if (s > bestv) { bestv = s; best = j; }
    }

    #pragma unroll
    for (int j = 0; j < 18; j++)
        #pragma unroll
        for (int c = 0; c < 3; c++)
            out[OFF_SRES + 54*g + j*3 + c] = nt[47 + j*3 + c] * msa[j*3 + c];

    float ps[3];
    #pragma unroll
    for (int c = 0; c < 3; c++) {
        ps[c] = nt[47 + best*3 + c] * msa[best*3 + c] + msa[best*3 + c];
        out[OFF_PSIZE + 3*g + c] = ps[c];
    }

    float mx = -1e30f;
    #pragma unroll
    for (int j = 0; j < 18; j++) {
        float s = nt[101 + j];
        out[OFF_SEM  + 18*g + j] = s;
        out[OFF_SLOG + 19*g + j] = s;
        mx = fmaxf(mx, s);
    }
    float e[18], sum = 0.0f;
    #pragma unroll
    for (int j = 0; j < 18; j++) { e[j] = expf(nt[101 + j] - mx); sum += e[j]; }
    #pragma unroll
    for (int j = 0; j < 18; j++) out[OFF_SPROB + 18*g + j] = e[j] / sum;

    out[OFF_SLOG + 19*g + 18] = (obj0 <= obj1) ? 0.0f : 1e10f;

    float m2 = fmaxf(obj0, obj1);
    float e0 = expf(obj0 - m2), e1 = expf(obj1 - m2);
    out[OFF_OPROB + g] = e1 / (e0 + e1);

    float cc0 = cen[0], cc1 = cen[2], cc2 = -cen[1];
    const float sxv[8] = {1,1,-1,-1,1,1,-1,-1};
    const float syv[8] = {1,1,1,1,-1,-1,-1,-1};
    const float szv[8] = {1,-1,-1,1,1,-1,-1,1};
    #pragma unroll
    for (int k = 0; k < 8; k++) {
        out[OFF_CORN + 24*g + k*3 + 0] = cc0 + ps[0] * sxv[k] * 0.5f;
        out[OFF_CORN + 24*g + k*3 + 1] = cc1 + ps[2] * syv[k] * 0.5f;
        out[OFF_CORN + 24*g + k*3 + 2] = cc2 + ps[1] * szv[k] * 0.5f;
    }
}

// ---------------- launch ----------------
extern "C" void kernel_launch(void* const* d_in, const int* in_sizes, int n_in,
                              void* d_out, int out_size) {
    const float* xyz      = (const float*)d_in[0];
    const float* features = (const float*)d_in[1];
    const float* sa_w1    = (const float*)d_in[2];
    const float* sa_w2    = (const float*)d_in[3];
    const float* sa_w3    = (const float*)d_in[4];
    const float* sa_gamma = (const float*)d_in[5];
    const float* sa_beta  = (const float*)d_in[6];
    const float* sa_mean  = (const float*)d_in[7];
    const float* sa_var   = (const float*)d_in[8];
    const float* p_w1     = (const float*)d_in[9];
    const float* p_w2     = (const float*)d_in[10];
    const float* p_w3     = (const float*)d_in[11];
    const float* p_b3     = (const float*)d_in[12];
    const float* p_gamma  = (const float*)d_in[13];
    const float* p_beta   = (const float*)d_in[14];
    const float* p_mean   = (const float*)d_in[15];
    const float* p_var    = (const float*)d_in[16];
    const float* msa      = (const float*)d_in[17];
    float* out = (float*)d_out;

    #define GA(sym) ({ void* _p; cudaGetSymbolAddress(&_p, sym); (float*)_p; })
    float* XTH = GA(d_xth); float* XTL = GA(d_xtl);
    float* A1H = GA(d_a1h); float* A1L = GA(d_a1l);
    float* A2H = GA(d_a2h); float* A2L = GA(d_a2l);
    float* A3  = GA(d_act3);
    float* YH  = GA(d_yh);  float* YL  = GA(d_yl);
    float* P1H = GA(d_p1h); float* P1L = GA(d_p1l);
    float* P2H = GA(d_p2h); float* P2L = GA(d_p2l);
    float* NET = GA(d_net);
    float* SB  = GA(d_sb);  float* ONE = GA(d_one); float* B3P = GA(d_b3p);
    float* W1H = GA(d_w1ph); float* W1L = GA(d_w1pl);
    float* W2H = GA(d_w2ph); float* W2L = GA(d_w2pl);
    float* W3H = GA(d_w3ph); float* W3L = GA(d_w3pl);
    float* Q1H = GA(d_pw1h); float* Q1L = GA(d_pw1l);
    float* Q2H = GA(d_pw2h); float* Q2L = GA(d_pw2l);
    float* HWH = GA(d_hwh);  float* HWL = GA(d_hwl);
    #undef GA

    cudaFuncSetAttribute(gemm_mma, cudaFuncAttributeMaxDynamicSharedMemorySize, GEMM_SMEM);

    permW_kernel<<<2*9*16, 256>>>(sa_w1, 256, 259, 9, W1H, W1L);
    permW_kernel<<<2*8*16, 256>>>(sa_w2, 256, 256, 8, W2H, W2L);
    permW_kernel<<<2*8*16, 256>>>(sa_w3, 256, 256, 8, W3H, W3L);
    permW_kernel<<<2*8*16, 256>>>(p_w1, 256, 256, 8, Q1H, Q1L);
    permW_kernel<<<2*8*16, 256>>>(p_w2, 256, 256, 8, Q2H, Q2L);
    permW_kernel<<<1*8*16, 256>>>(p_w3, OUTD, 256, 8, HWH, HWL);
    sb_kernel<<<6, 256>>>(sa_gamma, sa_beta, sa_mean, sa_var,
                          p_gamma, p_beta, p_mean, p_var, p_b3);
    fps_kernel<<<BB, 256>>>(xyz);
    bq_kernel<<<BB, 256>>>(xyz);
    transpose_kernel<<<dim3(KPTS/32, CFEAT/32, BB), dim3(32, 8)>>>(features);
    gather_kernel<<<PROPROW, 128>>>(xyz);

    // SA layers (1D grid, yb interleaved in low bit)
    gemm_mma<<<TOTROW/128*2, 256, GEMM_SMEM>>>(XTH, XTL, 9, W1H, W1L,
        A1H, A1L, 256, 9, SB + 0*512, SB + 0*512 + 256, 0, 1);
    gemm_mma<<<TOTROW/128*2, 256, GEMM_SMEM>>>(A1H, A1L, 8, W2H, W2L,
        A2H, A2L, 256, 8, SB + 1*512, SB + 1*512 + 256, 0, 1);
    gemm_mma<<<TOTROW/128*2, 256, GEMM_SMEM>>>(A2H, A2L, 8, W3H, W3L,
        A3, (float*)0, 256, 8, SB + 2*512, SB + 2*512 + 256, 0, 1);

    maxpool_kernel<<<PROPROW, 256>>>();

    // proposal layers
    gemm_mma<<<PROPROW/128*2, 256, GEMM_SMEM>>>(YH, YL, 8, Q1H, Q1L,
        P1H, P1L, 256, 8, SB + 3*512, SB + 3*512 + 256, 0, 1);
    gemm_mma<<<PROPROW/128*2, 256, GEMM_SMEM>>>(P1H, P1L, 8, Q2H, Q2L,
        P2H, P2L, 256, 8, SB + 4*512, SB + 4*512 + 256, 0, 1);
    gemm_mma<<<PROPROW/128, 256, GEMM_SMEM>>>(P2H, P2L, 8, HWH, HWL,
        NET, (float*)0, 128, 8, ONE, B3P, 1, 0);

    decode_kernel<<<PROPROW/256, 256>>>(msa, out);
}

// round 10
// speedup vs baseline: 1.6088x; 1.5855x over previous
#include <cuda_runtime.h>
#include <cuda_bf16.h>
#include <math.h>
#include <stdint.h>

#define BB 32
#define KPTS 2048
#define CFEAT 256
#define NPROP 256
#define NSAMP 16
#define NCOL 4096
#define K1P 288
#define OUTD 119
#define TOTROW (BB*NCOL)    // 131072
#define PROPROW (BB*NPROP)  // 8192

// B stage: 2048 uint32 hi + 2048 uint32 lo (bf16x2 packed) = 16KB; 2 stages
#define BSTU 4096
#define GEMM_SMEM ((2*BSTU + 256) * 4)   // 34816 bytes

// ---------------- scratch ----------------
__device__ float d_featT[(size_t)BB*KPTS*CFEAT];
__device__ uint32_t d_xth[(size_t)TOTROW*K1P/2];
__device__ uint32_t d_xtl[(size_t)TOTROW*K1P/2];
__device__ uint32_t d_a1h[(size_t)TOTROW*CFEAT/2];
__device__ uint32_t d_a1l[(size_t)TOTROW*CFEAT/2];
__device__ uint32_t d_a2h[(size_t)TOTROW*CFEAT/2];
__device__ uint32_t d_a2l[(size_t)TOTROW*CFEAT/2];
__device__ float d_act3[(size_t)TOTROW*CFEAT];
__device__ uint32_t d_yh [(size_t)PROPROW*CFEAT/2];
__device__ uint32_t d_yl [(size_t)PROPROW*CFEAT/2];
__device__ uint32_t d_p1h[(size_t)PROPROW*CFEAT/2];
__device__ uint32_t d_p1l[(size_t)PROPROW*CFEAT/2];
__device__ uint32_t d_p2h[(size_t)PROPROW*CFEAT/2];
__device__ uint32_t d_p2l[(size_t)PROPROW*CFEAT/2];
__device__ float d_net[(size_t)PROPROW*128];
__device__ float d_newxyz[PROPROW*3];
__device__ int   d_idxbuf[PROPROW*NSAMP];
__device__ float d_sb[5*2*256];
__device__ float d_one[256];
__device__ float d_b3p[128];
// permuted fragment-order weights, bf16x2 packed (hi/lo)
__device__ uint32_t d_w1ph[2*9*2048],  d_w1pl[2*9*2048];
__device__ uint32_t d_w2ph[2*8*2048],  d_w2pl[2*8*2048];
__device__ uint32_t d_w3ph[2*8*2048],  d_w3pl[2*8*2048];
__device__ uint32_t d_pw1h[2*8*2048],  d_pw1l[2*8*2048];
__device__ uint32_t d_pw2h[2*8*2048],  d_pw2l[2*8*2048];
__device__ uint32_t d_hwh [1*8*2048],  d_hwl [1*8*2048];

// ---------------- output layout offsets ----------------
#define OFF_OBJ    0LL
#define OFF_CENTER 16384LL
#define OFF_SSC    40960LL
#define OFF_SRES   188416LL
#define OFF_PSIZE  630784LL
#define OFF_SEM    655360LL
#define OFF_CORN   802816LL
#define OFF_SLOG   999424LL
#define OFF_OPROB  1155072LL
#define OFF_SPROB  1163264LL

__device__ __forceinline__ uint32_t smem_u32(const void* p) {
    uint32_t a;
    asm("{ .reg .u64 t; cvta.to.shared.u64 t, %1; cvt.u32.u64 %0, t; }" : "=r"(a) : "l"(p));
    return a;
}
__device__ __forceinline__ void cp16(uint32_t s, const void* g) {
    asm volatile("cp.async.cg.shared.global [%0], [%1], 16;" :: "r"(s), "l"(g));
}
#define CP_COMMIT() asm volatile("cp.async.commit_group;" ::: "memory")
#define CP_WAIT1()  asm volatile("cp.async.wait_group 1;" ::: "memory")
#define CP_WAIT0()  asm volatile("cp.async.wait_group 0;" ::: "memory")

__device__ __forceinline__ void mma_bf16(float* c, const uint32_t* a,
                                         uint32_t b0, uint32_t b1) {
    asm volatile(
        "mma.sync.aligned.m16n8k16.row.col.f32.bf16.bf16.f32 "
        "{%0,%1,%2,%3}, {%4,%5,%6,%7}, {%8,%9}, {%0,%1,%2,%3};"
        : "+f"(c[0]), "+f"(c[1]), "+f"(c[2]), "+f"(c[3])
        : "r"(a[0]), "r"(a[1]), "r"(a[2]), "r"(a[3]), "r"(b0), "r"(b1));
}

// bf16-element index for A-side fragment storage (m16n8k16 layout)
__device__ __forceinline__ size_t abf_off(int row, int k, int nk16) {
    size_t idx32 = ((size_t)(row >> 4) * nk16 + (k >> 4)) * 128
                 + (size_t)((row & 7) * 4 + ((k >> 1) & 3)) * 4
                 + ((row >> 3) & 1) + 2 * ((k >> 3) & 1);
    return idx32 * 2 + (k & 1);
}

__device__ __forceinline__ uint32_t pack2(float x, float y) {
    unsigned short lo = __bfloat16_as_ushort(__float2bfloat16_rn(x));
    unsigned short hi = __bfloat16_as_ushort(__float2bfloat16_rn(y));
    return (uint32_t)lo | ((uint32_t)hi << 16);
}
__device__ __forceinline__ float bf_round(float x) {
    return __bfloat162float(__float2bfloat16_rn(x));
}

// ============ 3xBF16 GEMM: B smem double-buffered, A direct LDG ============
__global__ __launch_bounds__(256, 2) void gemm_mma(
    const uint32_t* __restrict__ Ah, const uint32_t* __restrict__ Al, int nk16A,
    const uint32_t* __restrict__ Bph, const uint32_t* __restrict__ Bpl,
    float* __restrict__ Cf, uint32_t* __restrict__ Ch, uint32_t* __restrict__ Cl,
    int ldc, int nchunk,
    const float* __restrict__ scale, const float* __restrict__ bias,
    int mode, int nybm1)
{
    extern __shared__ uint32_t smu[];
    float* s_s = (float*)(smu + 2*BSTU);
    float* s_b = s_s + 128;
    const uint32_t smb = smem_u32(smu);

    const int tid = threadIdx.x;
    const int lane = tid & 31, wid = tid >> 5;
    const int wm = wid & 3, wn = wid >> 2;
    const int yb = blockIdx.x & nybm1;
    const long long xb = blockIdx.x >> nybm1;
    const long long m0 = xb * 128;
    const int y0 = yb * 128;
    const int lq = lane >> 2, lr = lane & 3;

    if (tid < 128) {
        s_s[tid] = (mode == 0) ? scale[y0 + tid] : 1.0f;
        s_b[tid] = bias[y0 + tid];
    }

    float acc[2][8][4];
    #pragma unroll
    for (int mt = 0; mt < 2; mt++)
        #pragma unroll
        for (int nt = 0; nt < 8; nt++)
            #pragma unroll
            for (int j = 0; j < 4; j++) acc[mt][nt][j] = 0.0f;

    // per-warp A fragment streams
    const size_t rbase0 = (size_t)(xb * 8 + wm * 2 + 0) * nk16A * 128 + lane * 4;
    const size_t rbase1 = rbase0 + (size_t)nk16A * 128;

    const size_t bbase = (size_t)yb * nchunk * 2048;

    auto stageB = [&](int kc) {
        const uint32_t sb0 = smb + (kc & 1) * BSTU * 4;
        const size_t bg = bbase + (size_t)kc * 2048;
        #pragma unroll
        for (int it = 0; it < 2; it++) {
            int idx = tid + it * 256;                 // 0..511 uint4 units
            cp16(sb0 + (uint32_t)idx * 16, Bph + bg + idx * 4);
            cp16(sb0 + 2048*4 + (uint32_t)idx * 16, Bpl + bg + idx * 4);
        }
    };

    stageB(0); CP_COMMIT();

    for (int kc = 0; kc < nchunk; kc++) {
        if (kc + 1 < nchunk) { stageB(kc + 1); CP_COMMIT(); CP_WAIT1(); }
        else CP_WAIT0();
        __syncthreads();

        const uint32_t* sBh = smu + (kc & 1) * BSTU;
        const uint32_t* sBl = sBh + 2048;

        #pragma unroll
        for (int k16l = 0; k16l < 2; k16l++) {
            const size_t ao = (size_t)(kc * 2 + k16l) * 128;
            uint4 ah0 = *(const uint4*)(Ah + rbase0 + ao);
            uint4 ah1 = *(const uint4*)(Ah + rbase1 + ao);
            uint4 al0 = *(const uint4*)(Al + rbase0 + ao);
            uint4 al1 = *(const uint4*)(Al + rbase1 + ao);
            uint2 bh[8], bl[8];
            #pragma unroll
            for (int nt = 0; nt < 8; nt++) {
                int fo = (k16l*16 + wn*8 + nt)*64 + lane*2;
                bh[nt] = *(const uint2*)(sBh + fo);
                bl[nt] = *(const uint2*)(sBl + fo);
            }
            #pragma unroll
            for (int nt = 0; nt < 8; nt++) {
                mma_bf16(acc[0][nt], (const uint32_t*)&al0, bh[nt].x, bh[nt].y);
                mma_bf16(acc[1][nt], (const uint32_t*)&al1, bh[nt].x, bh[nt].y);
            }
            #pragma unroll
            for (int nt = 0; nt < 8; nt++) {
                mma_bf16(acc[0][nt], (const uint32_t*)&ah0, bl[nt].x, bl[nt].y);
                mma_bf16(acc[1][nt], (const uint32_t*)&ah1, bl[nt].x, bl[nt].y);
            }
            #pragma unroll
            for (int nt = 0; nt < 8; nt++) {
                mma_bf16(acc[0][nt], (const uint32_t*)&ah0, bh[nt].x, bh[nt].y);
                mma_bf16(acc[1][nt], (const uint32_t*)&ah1, bh[nt].x, bh[nt].y);
            }
        }
        __syncthreads();
    }

    // ---- epilogue ----
    const int nk16o = ldc >> 4;
    #pragma unroll
    for (int mt = 0; mt < 2; mt++) {
        long long r0 = m0 + wm * 32 + mt * 16 + lq;
        size_t rb = (size_t)(m0 + wm * 32 + mt * 16) >> 4;
        #pragma unroll
        for (int nt = 0; nt < 8; nt++) {
            int gc = wn * 64 + nt * 8 + 2 * lr;
            float s0 = s_s[gc], s1 = s_s[gc + 1];
            float b0 = s_b[gc], b1 = s_b[gc + 1];
            float v00 = acc[mt][nt][0] * s0 + b0;
            float v01 = acc[mt][nt][1] * s1 + b1;
            float v10 = acc[mt][nt][2] * s0 + b0;
            float v11 = acc[mt][nt][3] * s1 + b1;
            if (mode == 0) {
                v00 = fmaxf(v00, 0.f); v01 = fmaxf(v01, 0.f);
                v10 = fmaxf(v10, 0.f); v11 = fmaxf(v11, 0.f);
            }
            if (Ch) {
                size_t blk = (rb * nk16o + (y0 >> 4) + wn * 4 + (nt >> 1)) * 128
                           + (size_t)(lq * 4 + lr) * 4 + 2 * (nt & 1);
                Ch[blk]     = pack2(v00, v01);
                Ch[blk + 1] = pack2(v10, v11);
                Cl[blk]     = pack2(v00 - bf_round(v00), v01 - bf_round(v01));
                Cl[blk + 1] = pack2(v10 - bf_round(v10), v11 - bf_round(v11));
            } else {
                *(float2*)(Cf + r0 * ldc + y0 + gc)       = make_float2(v00, v01);
                *(float2*)(Cf + (r0 + 8) * ldc + y0 + gc) = make_float2(v10, v11);
            }
        }
    }
}

// ---------------- weight permute (bf16 fragment order, hi/lo packed) --------
__global__ void permW_kernel(const float* __restrict__ W, int nrows, int ksrc,
                             int nkc, uint32_t* __restrict__ oh, uint32_t* __restrict__ ol) {
    int e = blockIdx.x * 256 + threadIdx.x;     // uint32 index
    int yb = e / (nkc * 2048);
    int rem = e - yb * nkc * 2048;
    int kc = rem >> 11;
    int w = rem & 2047;
    int k16l = w >> 10, ntile = (w >> 6) & 15, lane = (w >> 1) & 31, breg = w & 1;
    int o = yb * 128 + ntile * 8 + (lane >> 2);
    int k = kc * 32 + k16l * 16 + breg * 8 + (lane & 3) * 2;
    float v0 = (o < nrows && k     < ksrc) ? W[o * ksrc + k]     : 0.0f;
    float v1 = (o < nrows && k + 1 < ksrc) ? W[o * ksrc + k + 1] : 0.0f;
    oh[e] = pack2(v0, v1);
    ol[e] = pack2(v0 - bf_round(v0), v1 - bf_round(v1));
}

__global__ void sb_kernel(const float* __restrict__ sg, const float* __restrict__ sbe,
                          const float* __restrict__ sm, const float* __restrict__ sv,
                          const float* __restrict__ pg, const float* __restrict__ pb,
                          const float* __restrict__ pm, const float* __restrict__ pv,
                          const float* __restrict__ b3) {
    int l = blockIdx.x, t = threadIdx.x;
    if (l == 5) {
        if (t < 128) d_b3p[t] = (t < OUTD) ? b3[t] : 0.0f;
        d_one[t] = 1.0f;
        return;
    }
    float g, bt, m, v;
    if (l < 3) { g = sg[l*256+t]; bt = sbe[l*256+t]; m = sm[l*256+t]; v = sv[l*256+t]; }
    else { int q = l - 3; g = pg[q*256+t]; bt = pb[q*256+t]; m = pm[q*256+t]; v = pv[q*256+t]; }
    float s = g / sqrtf(v + 1e-5f);
    d_sb[l*512 + t] = s;
    d_sb[l*512 + 256 + t] = bt - m * s;
}

// ---------------- FPS ----------------
__global__ __launch_bounds__(256) void fps_kernel(const float* __restrict__ xyz) {
    __shared__ float sx[KPTS], sy[KPTS], sz[KPTS];
    __shared__ float wv_s[8];
    __shared__ int   wi_s[8];
    __shared__ int   sfar;
    int b = blockIdx.x, tid = threadIdx.x;
    const float* base = xyz + (size_t)b * KPTS * 3;
    for (int k = tid; k < KPTS; k += 256) {
        sx[k] = base[k*3+0]; sy[k] = base[k*3+1]; sz[k] = base[k*3+2];
    }
    float dreg[8];
    #pragma unroll
    for (int j = 0; j < 8; j++) dreg[j] = 1e10f;
    int far = 0;
    int warp = tid >> 5, lane = tid & 31;
    __syncthreads();
    for (int i = 0; i < NPROP; i++) {
        float cx = sx[far], cy = sy[far], cz = sz[far];
        if (tid == 0) {
            d_newxyz[(b*NPROP+i)*3+0] = cx;
            d_newxyz[(b*NPROP+i)*3+1] = cy;
            d_newxyz[(b*NPROP+i)*3+2] = cz;
        }
        float bv = -1.0f; int bi = 0x7fffffff;
        #pragma unroll
        for (int j = 0; j < 8; j++) {
            int k = tid + j * 256;
            float dx = sx[k]-cx, dy = sy[k]-cy, dz = sz[k]-cz;
            float d = __fadd_rn(__fadd_rn(__fmul_rn(dx,dx), __fmul_rn(dy,dy)), __fmul_rn(dz,dz));
            dreg[j] = fminf(dreg[j], d);
            if (dreg[j] > bv) { bv = dreg[j]; bi = k; }
        }
        unsigned bvb = __float_as_uint(bv);
        unsigned vmax = __reduce_max_sync(0xffffffffu, bvb);
        unsigned cand = (bvb == vmax) ? (unsigned)bi : 0x7fffffffu;
        unsigned bidx = __reduce_min_sync(0xffffffffu, cand);
        if (lane == 0) { wv_s[warp] = __uint_as_float(vmax); wi_s[warp] = (int)bidx; }
        __syncthreads();
        if (warp == 0) {
            unsigned v = (lane < 8) ? __float_as_uint(wv_s[lane]) : 0u;
            unsigned ii = (lane < 8) ? (unsigned)wi_s[lane] : 0x7fffffffu;
            unsigned vm = __reduce_max_sync(0xffffffffu, v);
            unsigned c2 = (v == vm) ? ii : 0x7fffffffu;
            unsigned idx = __reduce_min_sync(0xffffffffu, c2);
            if (lane == 0) sfar = (int)idx;
        }
        __syncthreads();
        far = sfar;
    }
}

// ---------------- ball query ----------------
__global__ __launch_bounds__(256) void bq_kernel(const float* __restrict__ xyz) {
    __shared__ float sx[KPTS], sy[KPTS], sz[KPTS];
    int b = blockIdx.x, tid = threadIdx.x;
    const float* base = xyz + (size_t)b * KPTS * 3;
    for (int k = tid; k < KPTS; k += 256) {
        sx[k] = base[k*3+0]; sy[k] = base[k*3+1]; sz[k] = base[k*3+2];
    }
    __syncthreads();
    int p = tid;
    float nx = d_newxyz[(b*NPROP+p)*3+0];
    float ny = d_newxyz[(b*NPROP+p)*3+1];
    float nz = d_newxyz[(b*NPROP+p)*3+2];
    int* dst = d_idxbuf + (b*NPROP+p)*NSAMP;
    int cnt = 0, first = 0;
    const float R2 = 0.09f;
    for (int k = 0; k < KPTS; k++) {
        float dx = sx[k]-nx, dy = sy[k]-ny, dz = sz[k]-nz;
        float d = __fadd_rn(__fadd_rn(__fmul_rn(dx,dx), __fmul_rn(dy,dy)), __fmul_rn(dz,dz));
        if (d < R2) {
            if (cnt == 0) first = k;
            dst[cnt] = k;
            if (++cnt == NSAMP) break;
        }
    }
    for (int j = cnt; j < NSAMP; j++) dst[j] = first;
}

// ---------------- feature transpose ----------------
__global__ void transpose_kernel(const float* __restrict__ in) {
    __shared__ float tile[32][33];
    int b = blockIdx.z;
    int k0 = blockIdx.x * 32, c0 = blockIdx.y * 32;
    const float* src = in + (size_t)b * CFEAT * KPTS;
    float* dst = d_featT + (size_t)b * KPTS * CFEAT;
    int tx = threadIdx.x, ty = threadIdx.y;
    #pragma unroll
    for (int i = 0; i < 4; i++)
        tile[ty + i*8][tx] = src[(size_t)(c0 + ty + i*8) * KPTS + k0 + tx];
    __syncthreads();
    #pragma unroll
    for (int i = 0; i < 4; i++)
        dst[(size_t)(k0 + ty + i*8) * CFEAT + c0 + tx] = tile[tx][ty + i*8];
}

// ---------------- gather: Xt hi/lo bf16 in fragment order ----------------
__global__ __launch_bounds__(128) void gather_kernel(const float* __restrict__ xyz) {
    int blk = blockIdx.x;
    int b = blk >> 8;
    int tid = threadIdx.x;
    __shared__ int   ks[NSAMP];
    __shared__ float cxyz[3];
    if (tid < NSAMP) ks[tid] = d_idxbuf[blk*NSAMP + tid];
    if (tid < 3)     cxyz[tid] = d_newxyz[blk*3 + tid];
    __syncthreads();
    __nv_bfloat16* xth = (__nv_bfloat16*)d_xth;
    __nv_bfloat16* xtl = (__nv_bfloat16*)d_xtl;
    for (int s = 0; s < NSAMP; s++) {
        int k = ks[s];
        const float* frow = d_featT + ((size_t)b * KPTS + k) * CFEAT;
        const float* prow = xyz + ((size_t)b * KPTS + k) * 3;
        int row = blk * NSAMP + s;
        for (int c = tid; c < K1P; c += 128) {
            float v;
            if (c < 3)        v = (prow[c] - cxyz[c]) / 0.3f;
            else if (c < 259) v = frow[c-3];
            else              v = 0.0f;
            size_t o = abf_off(row, c, 18);
            xth[o] = __float2bfloat16_rn(v);
            xtl[o] = __float2bfloat16_rn(v - bf_round(v));
        }
    }
}

// ---------------- maxpool: act3 -> Y hi/lo bf16 (fragment order) -----------
__global__ __launch_bounds__(256) void maxpool_kernel() {
    int blk = blockIdx.x;
    int c = threadIdx.x;
    const float* src = d_act3 + (size_t)blk * NSAMP * CFEAT;
    float m = src[c];
    #pragma unroll
    for (int s = 1; s < NSAMP; s++) m = fmaxf(m, src[s*CFEAT + c]);
    size_t o = abf_off(blk, c, 16);
    ((__nv_bfloat16*)d_yh)[o] = __float2bfloat16_rn(m);
    ((__nv_bfloat16*)d_yl)[o] = __float2bfloat16_rn(m - bf_round(m));
}

// ---------------- decode head ----------------
__global__ __launch_bounds__(256) void decode_kernel(const float* __restrict__ msa,
                                                     float* __restrict__ out) {
    int g = blockIdx.x * 256 + threadIdx.x;
    if (g >= PROPROW) return;
    const float* nt = d_net + (size_t)g * 128;
    const float* nx = d_newxyz + (size_t)g * 3;

    float obj0 = nt[0], obj1 = nt[1];
    out[OFF_OBJ + 2*g + 0] = obj0;
    out[OFF_OBJ + 2*g + 1] = obj1;

    float cen[3];
    #pragma unroll
    for (int c = 0; c < 3; c++) {
        cen[c] = nx[c] + nt[2 + c];
        out[OFF_CENTER + 3*g + c] = cen[c];
    }

    float bestv = -1e30f; int best = 0;
    #pragma unroll
    for (int j = 0; j < 18; j++) {
        float s = nt[29 + j];
        out[OFF_SSC + 18*g + j] = s;
        if (s > bestv) { bestv = s; best = j; }
    }

    #pragma unroll
    for (int j = 0; j < 18; j++)
        #pragma unroll
        for (int c = 0; c < 3; c++)
            out[OFF_SRES + 54*g + j*3 + c] = nt[47 + j*3 + c] * msa[j*3 + c];

    float ps[3];
    #pragma unroll
    for (int c = 0; c < 3; c++) {
        ps[c] = nt[47 + best*3 + c] * msa[best*3 + c] + msa[best*3 + c];
        out[OFF_PSIZE + 3*g + c] = ps[c];
    }

    float mx = -1e30f;
    #pragma unroll
    for (int j = 0; j < 18; j++) {
        float s = nt[101 + j];
        out[OFF_SEM  + 18*g + j] = s;
        out[OFF_SLOG + 19*g + j] = s;
        mx = fmaxf(mx, s);
    }
    float e[18], sum = 0.0f;
    #pragma unroll
    for (int j = 0; j < 18; j++) { e[j] = expf(nt[101 + j] - mx); sum += e[j]; }
    #pragma unroll
    for (int j = 0; j < 18; j++) out[OFF_SPROB + 18*g + j] = e[j] / sum;

    out[OFF_SLOG + 19*g + 18] = (obj0 <= obj1) ? 0.0f : 1e10f;

    float m2 = fmaxf(obj0, obj1);
    float e0 = expf(obj0 - m2), e1 = expf(obj1 - m2);
    out[OFF_OPROB + g] = e1 / (e0 + e1);

    float cc0 = cen[0], cc1 = cen[2], cc2 = -cen[1];
    const float sxv[8] = {1,1,-1,-1,1,1,-1,-1};
    const float syv[8] = {1,1,1,1,-1,-1,-1,-1};
    const float szv[8] = {1,-1,-1,1,1,-1,-1,1};
    #pragma unroll
    for (int k = 0; k < 8; k++) {
        out[OFF_CORN + 24*g + k*3 + 0] = cc0 + ps[0] * sxv[k] * 0.5f;
        out[OFF_CORN + 24*g + k*3 + 1] = cc1 + ps[2] * syv[k] * 0.5f;
        out[OFF_CORN + 24*g + k*3 + 2] = cc2 + ps[1] * szv[k] * 0.5f;
    }
}

// ---------------- launch ----------------
extern "C" void kernel_launch(void* const* d_in, const int* in_sizes, int n_in,
                              void* d_out, int out_size) {
    const float* xyz      = (const float*)d_in[0];
    const float* features = (const float*)d_in[1];
    const float* sa_w1    = (const float*)d_in[2];
    const float* sa_w2    = (const float*)d_in[3];
    const float* sa_w3    = (const float*)d_in[4];
    const float* sa_gamma = (const float*)d_in[5];
    const float* sa_beta  = (const float*)d_in[6];
    const float* sa_mean  = (const float*)d_in[7];
    const float* sa_var   = (const float*)d_in[8];
    const float* p_w1     = (const float*)d_in[9];
    const float* p_w2     = (const float*)d_in[10];
    const float* p_w3     = (const float*)d_in[11];
    const float* p_b3     = (const float*)d_in[12];
    const float* p_gamma  = (const float*)d_in[13];
    const float* p_beta   = (const float*)d_in[14];
    const float* p_mean   = (const float*)d_in[15];
    const float* p_var    = (const float*)d_in[16];
    const float* msa      = (const float*)d_in[17];
    float* out = (float*)d_out;

    #define GAU(sym) ({ void* _p; cudaGetSymbolAddress(&_p, sym); (uint32_t*)_p; })
    #define GAF(sym) ({ void* _p; cudaGetSymbolAddress(&_p, sym); (float*)_p; })
    uint32_t* XTH = GAU(d_xth); uint32_t* XTL = GAU(d_xtl);
    uint32_t* A1H = GAU(d_a1h); uint32_t* A1L = GAU(d_a1l);
    uint32_t* A2H = GAU(d_a2h); uint32_t* A2L = GAU(d_a2l);
    float* A3  = GAF(d_act3);
    uint32_t* YH  = GAU(d_yh);  uint32_t* YL  = GAU(d_yl);
    uint32_t* P1H = GAU(d_p1h); uint32_t* P1L = GAU(d_p1l);
    uint32_t* P2H = GAU(d_p2h); uint32_t* P2L = GAU(d_p2l);
    float* NET = GAF(d_net);
    float* SB  = GAF(d_sb);  float* ONE = GAF(d_one); float* B3P = GAF(d_b3p);
    uint32_t* W1H = GAU(d_w1ph); uint32_t* W1L = GAU(d_w1pl);
    uint32_t* W2H = GAU(d_w2ph); uint32_t* W2L = GAU(d_w2pl);
    uint32_t* W3H = GAU(d_w3ph); uint32_t* W3L = GAU(d_w3pl);
    uint32_t* Q1H = GAU(d_pw1h); uint32_t* Q1L = GAU(d_pw1l);
    uint32_t* Q2H = GAU(d_pw2h); uint32_t* Q2L = GAU(d_pw2l);
    uint32_t* HWH = GAU(d_hwh);  uint32_t* HWL = GAU(d_hwl);
    #undef GAU
    #undef GAF

    cudaFuncSetAttribute(gemm_mma, cudaFuncAttributeMaxDynamicSharedMemorySize, GEMM_SMEM);

    permW_kernel<<<2*9*8, 256>>>(sa_w1, 256, 259, 9, W1H, W1L);
    permW_kernel<<<2*8*8, 256>>>(sa_w2, 256, 256, 8, W2H, W2L);
    permW_kernel<<<2*8*8, 256>>>(sa_w3, 256, 256, 8, W3H, W3L);
    permW_kernel<<<2*8*8, 256>>>(p_w1, 256, 256, 8, Q1H, Q1L);
    permW_kernel<<<2*8*8, 256>>>(p_w2, 256, 256, 8, Q2H, Q2L);
    permW_kernel<<<1*8*8, 256>>>(p_w3, OUTD, 256, 8, HWH, HWL);
    sb_kernel<<<6, 256>>>(sa_gamma, sa_beta, sa_mean, sa_var,
                          p_gamma, p_beta, p_mean, p_var, p_b3);
    fps_kernel<<<BB, 256>>>(xyz);
    bq_kernel<<<BB, 256>>>(xyz);
    transpose_kernel<<<dim3(KPTS/32, CFEAT/32, BB), dim3(32, 8)>>>(features);
    gather_kernel<<<PROPROW, 128>>>(xyz);

    // SA layers (1D grid, yb interleaved in low bit)
    gemm_mma<<<TOTROW/128*2, 256, GEMM_SMEM>>>(XTH, XTL, 18, W1H, W1L,
        (float*)0, A1H, A1L, 256, 9, SB + 0*512, SB + 0*512 + 256, 0, 1);
    gemm_mma<<<TOTROW/128*2, 256, GEMM_SMEM>>>(A1H, A1L, 16, W2H, W2L,
        (float*)0, A2H, A2L, 256, 8, SB + 1*512, SB + 1*512 + 256, 0, 1);
    gemm_mma<<<TOTROW/128*2, 256, GEMM_SMEM>>>(A2H, A2L, 16, W3H, W3L,
        A3, (uint32_t*)0, (uint32_t*)0, 256, 8, SB + 2*512, SB + 2*512 + 256, 0, 1);

    maxpool_kernel<<<PROPROW, 256>>>();

    // proposal layers
    gemm_mma<<<PROPROW/128*2, 256, GEMM_SMEM>>>(YH, YL, 16, Q1H, Q1L,
        (float*)0, P1H, P1L, 256, 8, SB + 3*512, SB + 3*512 + 256, 0, 1);
    gemm_mma<<<PROPROW/128*2, 256, GEMM_SMEM>>>(P1H, P1L, 16, Q2H, Q2L,
        (float*)0, P2H, P2L, 256, 8, SB + 4*512, SB + 4*512 + 256, 0, 1);
    gemm_mma<<<PROPROW/128, 256, GEMM_SMEM>>>(P2H, P2L, 16, HWH, HWL,
        NET, (uint32_t*)0, (uint32_t*)0, 128, 8, ONE, B3P, 1, 0);

    decode_kernel<<<PROPROW/256, 256>>>(msa, out);
}

// round 14
// speedup vs baseline: 1.8318x; 1.1386x over previous
#include <cuda_runtime.h>
#include <cuda_bf16.h>
#include <math.h>
#include <stdint.h>

#define BB 32
#define KPTS 2048
#define CFEAT 256
#define NPROP 256
#define NSAMP 16
#define OUTD 119
#define TOTROW (BB*16*NPROP)   // 131072
#define PTROW  (BB*KPTS)       // 65536
#define PROPROW (BB*NPROP)     // 8192

#define BSTU 4096
#define GEMM_SMEM ((2*BSTU + 256) * 4)   // 34816 bytes

// ---------------- scratch ----------------
__device__ uint32_t d_fth[(size_t)PTROW*CFEAT/2];   // per-point features, bf16 frag
__device__ uint32_t d_ftl[(size_t)PTROW*CFEAT/2];
__device__ uint32_t d_a1h[(size_t)TOTROW*CFEAT/2];
__device__ uint32_t d_a1l[(size_t)TOTROW*CFEAT/2];
__device__ uint32_t d_a2h[(size_t)TOTROW*CFEAT/2];
__device__ uint32_t d_a2l[(size_t)TOTROW*CFEAT/2];
__device__ float d_act3[(size_t)TOTROW*CFEAT];      // also reused as G (65536x256)
__device__ uint32_t d_yh [(size_t)PROPROW*CFEAT/2];
__device__ uint32_t d_yl [(size_t)PROPROW*CFEAT/2];
__device__ uint32_t d_p1h[(size_t)PROPROW*CFEAT/2];
__device__ uint32_t d_p1l[(size_t)PROPROW*CFEAT/2];
__device__ uint32_t d_p2h[(size_t)PROPROW*CFEAT/2];
__device__ uint32_t d_p2l[(size_t)PROPROW*CFEAT/2];
__device__ float d_net[(size_t)PROPROW*128];
__device__ float d_newxyz[PROPROW*3];
__device__ int   d_idxbuf[PROPROW*NSAMP];
__device__ float d_sb[5*2*256];
__device__ float d_one[256];
__device__ float d_zero[256];
__device__ float d_b3p[128];
__device__ float d_wxyz[256*4];
__device__ uint32_t d_w1ph[2*8*2048],  d_w1pl[2*8*2048];
__device__ uint32_t d_w2ph[2*8*2048],  d_w2pl[2*8*2048];
__device__ uint32_t d_w3ph[2*8*2048],  d_w3pl[2*8*2048];
__device__ uint32_t d_pw1h[2*8*2048],  d_pw1l[2*8*2048];
__device__ uint32_t d_pw2h[2*8*2048],  d_pw2l[2*8*2048];
__device__ uint32_t d_hwh [1*8*2048],  d_hwl [1*8*2048];

// ---------------- output layout offsets ----------------
#define OFF_OBJ    0LL
#define OFF_CENTER 16384LL
#define OFF_SSC    40960LL
#define OFF_SRES   188416LL
#define OFF_PSIZE  630784LL
#define OFF_SEM    655360LL
#define OFF_CORN   802816LL
#define OFF_SLOG   999424LL
#define OFF_OPROB  1155072LL
#define OFF_SPROB  1163264LL

__device__ __forceinline__ uint32_t smem_u32(const void* p) {
    uint32_t a;
    asm("{ .reg .u64 t; cvta.to.shared.u64 t, %1; cvt.u32.u64 %0, t; }" : "=r"(a) : "l"(p));
    return a;
}
__device__ __forceinline__ void cp16(uint32_t s, const void* g) {
    asm volatile("cp.async.cg.shared.global [%0], [%1], 16;" :: "r"(s), "l"(g));
}
#define CP_COMMIT() asm volatile("cp.async.commit_group;" ::: "memory")
#define CP_WAIT1()  asm volatile("cp.async.wait_group 1;" ::: "memory")
#define CP_WAIT0()  asm volatile("cp.async.wait_group 0;" ::: "memory")

__device__ __forceinline__ void mma_bf16(float* c, const uint32_t* a,
                                         uint32_t b0, uint32_t b1) {
    asm volatile(
        "mma.sync.aligned.m16n8k16.row.col.f32.bf16.bf16.f32 "
        "{%0,%1,%2,%3}, {%4,%5,%6,%7}, {%8,%9}, {%0,%1,%2,%3};"
        : "+f"(c[0]), "+f"(c[1]), "+f"(c[2]), "+f"(c[3])
        : "r"(a[0]), "r"(a[1]), "r"(a[2]), "r"(a[3]), "r"(b0), "r"(b1));
}

// uint32 index for A-frag pair (c even)
__device__ __forceinline__ size_t abf32_off(int row, int c, int nk16) {
    return ((size_t)(row >> 4) * nk16 + (c >> 4)) * 128
         + (size_t)((row & 7) * 4 + ((c >> 1) & 3)) * 4
         + ((row >> 3) & 1) + 2 * ((c >> 3) & 1);
}

__device__ __forceinline__ uint32_t pack2(float x, float y) {
    unsigned short lo = __bfloat16_as_ushort(__float2bfloat16_rn(x));
    unsigned short hi = __bfloat16_as_ushort(__float2bfloat16_rn(y));
    return (uint32_t)lo | ((uint32_t)hi << 16);
}
__device__ __forceinline__ float bf_round(float x) {
    return __bfloat162float(__float2bfloat16_rn(x));
}

// ============ 3xBF16 GEMM: B smem double-buffered, A direct LDG ============
__global__ __launch_bounds__(256, 2) void gemm_mma(
    const uint32_t* __restrict__ Ah, const uint32_t* __restrict__ Al, int nk16A,
    const uint32_t* __restrict__ Bph, const uint32_t* __restrict__ Bpl,
    float* __restrict__ Cf, uint32_t* __restrict__ Ch, uint32_t* __restrict__ Cl,
    int ldc, int nchunk,
    const float* __restrict__ scale, const float* __restrict__ bias,
    int mode, int nybm1)
{
    extern __shared__ uint32_t smu[];
    float* s_s = (float*)(smu + 2*BSTU);
    float* s_b = s_s + 128;
    const uint32_t smb = smem_u32(smu);

    const int tid = threadIdx.x;
    const int lane = tid & 31, wid = tid >> 5;
    const int wm = wid & 3, wn = wid >> 2;
    const int yb = blockIdx.x & nybm1;
    const long long xb = blockIdx.x >> nybm1;
    const long long m0 = xb * 128;
    const int y0 = yb * 128;
    const int lq = lane >> 2, lr = lane & 3;

    if (tid < 128) {
        s_s[tid] = (mode == 0) ? scale[y0 + tid] : 1.0f;
        s_b[tid] = bias[y0 + tid];
    }

    float acc[2][8][4];
    #pragma unroll
    for (int mt = 0; mt < 2; mt++)
        #pragma unroll
        for (int nt = 0; nt < 8; nt++)
            #pragma unroll
            for (int j = 0; j < 4; j++) acc[mt][nt][j] = 0.0f;

    const size_t rbase0 = (size_t)(xb * 8 + wm * 2 + 0) * nk16A * 128 + lane * 4;
    const size_t rbase1 = rbase0 + (size_t)nk16A * 128;

    const size_t bbase = (size_t)yb * nchunk * 2048;

    auto stageB = [&](int kc) {
        const uint32_t sb0 = smb + (kc & 1) * BSTU * 4;
        const size_t bg = bbase + (size_t)kc * 2048;
        #pragma unroll
        for (int it = 0; it < 2; it++) {
            int idx = tid + it * 256;
            cp16(sb0 + (uint32_t)idx * 16, Bph + bg + idx * 4);
            cp16(sb0 + 2048*4 + (uint32_t)idx * 16, Bpl + bg + idx * 4);
        }
    };

    stageB(0); CP_COMMIT();

    for (int kc = 0; kc < nchunk; kc++) {
        if (kc + 1 < nchunk) { stageB(kc + 1); CP_COMMIT(); CP_WAIT1(); }
        else CP_WAIT0();
        __syncthreads();

        const uint32_t* sBh = smu + (kc & 1) * BSTU;
        const uint32_t* sBl = sBh + 2048;

        #pragma unroll
        for (int k16l = 0; k16l < 2; k16l++) {
            const size_t ao = (size_t)(kc * 2 + k16l) * 128;
            uint4 ah0 = *(const uint4*)(Ah + rbase0 + ao);
            uint4 ah1 = *(const uint4*)(Ah + rbase1 + ao);
            uint4 al0 = *(const uint4*)(Al + rbase0 + ao);
            uint4 al1 = *(const uint4*)(Al + rbase1 + ao);
            uint2 bh[8], bl[8];
            #pragma unroll
            for (int nt = 0; nt < 8; nt++) {
                int fo = (k16l*16 + wn*8 + nt)*64 + lane*2;
                bh[nt] = *(const uint2*)(sBh + fo);
                bl[nt] = *(const uint2*)(sBl + fo);
            }
            #pragma unroll
            for (int nt = 0; nt < 8; nt++) {
                mma_bf16(acc[0][nt], (const uint32_t*)&al0, bh[nt].x, bh[nt].y);
                mma_bf16(acc[1][nt], (const uint32_t*)&al1, bh[nt].x, bh[nt].y);
            }
            #pragma unroll
            for (int nt = 0; nt < 8; nt++) {
                mma_bf16(acc[0][nt], (const uint32_t*)&ah0, bl[nt].x, bl[nt].y);
                mma_bf16(acc[1][nt], (const uint32_t*)&ah1, bl[nt].x, bl[nt].y);
            }
            #pragma unroll
            for (int nt = 0; nt < 8; nt++) {
                mma_bf16(acc[0][nt], (const uint32_t*)&ah0, bh[nt].x, bh[nt].y);
                mma_bf16(acc[1][nt], (const uint32_t*)&ah1, bh[nt].x, bh[nt].y);
            }
        }
        __syncthreads();
    }

    const int nk16o = ldc >> 4;
    #pragma unroll
    for (int mt = 0; mt < 2; mt++) {
        long long r0 = m0 + wm * 32 + mt * 16 + lq;
        size_t rb = (size_t)(m0 + wm * 32 + mt * 16) >> 4;
        #pragma unroll
        for (int nt = 0; nt < 8; nt++) {
            int gc = wn * 64 + nt * 8 + 2 * lr;
            float s0 = s_s[gc], s1 = s_s[gc + 1];
            float b0 = s_b[gc], b1 = s_b[gc + 1];
            float v00 = acc[mt][nt][0] * s0 + b0;
            float v01 = acc[mt][nt][1] * s1 + b1;
            float v10 = acc[mt][nt][2] * s0 + b0;
            float v11 = acc[mt][nt][3] * s1 + b1;
            if (mode == 0) {
                v00 = fmaxf(v00, 0.f); v01 = fmaxf(v01, 0.f);
                v10 = fmaxf(v10, 0.f); v11 = fmaxf(v11, 0.f);
            }
            if (Ch) {
                size_t blk = (rb * nk16o + (y0 >> 4) + wn * 4 + (nt >> 1)) * 128
                           + (size_t)(lq * 4 + lr) * 4 + 2 * (nt & 1);
                Ch[blk]     = pack2(v00, v01);
                Ch[blk + 1] = pack2(v10, v11);
                Cl[blk]     = pack2(v00 - bf_round(v00), v01 - bf_round(v01));
                Cl[blk + 1] = pack2(v10 - bf_round(v10), v11 - bf_round(v11));
            } else {
                *(float2*)(Cf + r0 * ldc + y0 + gc)       = make_float2(v00, v01);
                *(float2*)(Cf + (r0 + 8) * ldc + y0 + gc) = make_float2(v10, v11);
            }
        }
    }
}

// ---------------- weight permute (bf16 frag order, hi/lo, with col offset) --
__global__ void permW_kernel(const float* __restrict__ W, int nrows, int ld,
                             int koff, int kdim,
                             uint32_t* __restrict__ oh, uint32_t* __restrict__ ol) {
    int nkc = kdim >> 5;
    int e = blockIdx.x * 256 + threadIdx.x;
    int yb = e / (nkc * 2048);
    int rem = e - yb * nkc * 2048;
    int kc = rem >> 11;
    int w = rem & 2047;
    int k16l = w >> 10, ntile = (w >> 6) & 15, lane = (w >> 1) & 31, breg = w & 1;
    int o = yb * 128 + ntile * 8 + (lane >> 2);
    int k = kc * 32 + k16l * 16 + breg * 8 + (lane & 3) * 2;
    float v0 = (o < nrows && k     < kdim) ? W[o * ld + koff + k]     : 0.0f;
    float v1 = (o < nrows && k + 1 < kdim) ? W[o * ld + koff + k + 1] : 0.0f;
    oh[e] = pack2(v0, v1);
    ol[e] = pack2(v0 - bf_round(v0), v1 - bf_round(v1));
}

__global__ void sb_kernel(const float* __restrict__ sg, const float* __restrict__ sbe,
                          const float* __restrict__ sm, const float* __restrict__ sv,
                          const float* __restrict__ pg, const float* __restrict__ pb,
                          const float* __restrict__ pm, const float* __restrict__ pv,
                          const float* __restrict__ b3, const float* __restrict__ w1) {
    int l = blockIdx.x, t = threadIdx.x;
    if (l == 5) {
        if (t < 128) d_b3p[t] = (t < OUTD) ? b3[t] : 0.0f;
        d_one[t] = 1.0f;
        d_zero[t] = 0.0f;
        return;
    }
    if (l == 6) {
        d_wxyz[t*4+0] = w1[t*259+0];
        d_wxyz[t*4+1] = w1[t*259+1];
        d_wxyz[t*4+2] = w1[t*259+2];
        d_wxyz[t*4+3] = 0.0f;
        return;
    }
    float g, bt, m, v;
    if (l < 3) { g = sg[l*256+t]; bt = sbe[l*256+t]; m = sm[l*256+t]; v = sv[l*256+t]; }
    else { int q = l - 3; g = pg[q*256+t]; bt = pb[q*256+t]; m = pm[q*256+t]; v = pv[q*256+t]; }
    float s = g / sqrtf(v + 1e-5f);
    d_sb[l*512 + t] = s;
    d_sb[l*512 + 256 + t] = bt - m * s;
}

// ---------------- FPS (single barrier per iteration) ----------------
__global__ __launch_bounds__(256) void fps_kernel(const float* __restrict__ xyz) {
    __shared__ float sx[KPTS], sy[KPTS], sz[KPTS];
    __shared__ unsigned long long skey[2][8];
    int b = blockIdx.x, tid = threadIdx.x;
    const float* base = xyz + (size_t)b * KPTS * 3;
    for (int k = tid; k < KPTS; k += 256) {
        sx[k] = base[k*3+0]; sy[k] = base[k*3+1]; sz[k] = base[k*3+2];
    }
    float dreg[8];
    #pragma unroll
    for (int j = 0; j < 8; j++) dreg[j] = 1e10f;
    int far = 0;
    int warp = tid >> 5, lane = tid & 31;
    __syncthreads();
    for (int i = 0; i < NPROP; i++) {
        float cx = sx[far], cy = sy[far], cz = sz[far];
        if (tid == 0) {
            d_newxyz[(b*NPROP+i)*3+0] = cx;
            d_newxyz[(b*NPROP+i)*3+1] = cy;
            d_newxyz[(b*NPROP+i)*3+2] = cz;
        }
        float bv = -1.0f; int bi = 0x7fffffff;
        #pragma unroll
        for (int j = 0; j < 8; j++) {
            int k = tid + j * 256;
            float dx = sx[k]-cx, dy = sy[k]-cy, dz = sz[k]-cz;
            float d = __fadd_rn(__fadd_rn(__fmul_rn(dx,dx), __fmul_rn(dy,dy)), __fmul_rn(dz,dz));
            dreg[j] = fminf(dreg[j], d);
            if (dreg[j] > bv) { bv = dreg[j]; bi = k; }
        }
        unsigned bvb = __float_as_uint(bv);
        unsigned vmax = __reduce_max_sync(0xffffffffu, bvb);
        unsigned cand = (bvb == vmax) ? (unsigned)bi : 0x7fffffffu;
        unsigned bidx = __reduce_min_sync(0xffffffffu, cand);
        if (lane == 0)
            skey[i & 1][warp] = ((unsigned long long)vmax << 32)
                              | (unsigned)(0x7fffffffu - bidx);
        __syncthreads();
        unsigned long long best = 0;
        #pragma unroll
        for (int w = 0; w < 8; w++) {
            unsigned long long kk = skey[i & 1][w];
            if (kk > best) best = kk;
        }
        far = (int)(0x7fffffffu - (unsigned)(best & 0xffffffffu));
    }
}

// ---------------- ball query: one warp per proposal ----------------
__global__ __launch_bounds__(256) void bq_kernel(const float* __restrict__ xyz) {
    int w = threadIdx.x >> 5, lane = threadIdx.x & 31;
    int p = blockIdx.x * 8 + w;
    int b = p >> 8;
    const float* base = xyz + (size_t)b * KPTS * 3;
    float nx = d_newxyz[p*3+0];
    float ny = d_newxyz[p*3+1];
    float nz = d_newxyz[p*3+2];
    int* dst = d_idxbuf + p * NSAMP;
    int cnt = 0, first = 0;
    const float R2 = 0.09f;
    for (int ch = 0; ch < KPTS/32; ch++) {
        int k = ch * 32 + lane;
        float dx = base[k*3+0]-nx, dy = base[k*3+1]-ny, dz = base[k*3+2]-nz;
        float d = __fadd_rn(__fadd_rn(__fmul_rn(dx,dx), __fmul_rn(dy,dy)), __fmul_rn(dz,dz));
        bool in = d < R2;
        unsigned mask = __ballot_sync(0xffffffffu, in);
        if (cnt == 0 && mask) first = ch * 32 + __ffs(mask) - 1;
        if (in) {
            int slot = cnt + __popc(mask & ((1u << lane) - 1u));
            if (slot < NSAMP) dst[slot] = k;
        }
        cnt += __popc(mask);
        if (cnt >= NSAMP) break;
    }
    if (cnt < NSAMP && lane >= cnt && lane < NSAMP) dst[lane] = first;
}

// ---------------- transpose features -> bf16 hi/lo frags ----------------
__global__ void transfrag_kernel(const float* __restrict__ in) {
    __shared__ float tile[32][33];
    __shared__ uint32_t fh[512], fl[512];
    int b = blockIdx.z;
    int k0 = blockIdx.x * 32, c0 = blockIdx.y * 32;
    const float* src = in + (size_t)b * CFEAT * KPTS;
    int tx = threadIdx.x, ty = threadIdx.y;
    #pragma unroll
    for (int i = 0; i < 4; i++)
        tile[ty + i*8][tx] = src[(size_t)(c0 + ty + i*8) * KPTS + k0 + tx];
    __syncthreads();
    int t = ty * 32 + tx;
    #pragma unroll
    for (int uu = 0; uu < 2; uu++) {
        int u = t + uu * 256;
        int r = u & 31, cp = u >> 5;       // r = k_local, cp = col pair 0..15
        float v0 = tile[cp*2][r], v1 = tile[cp*2+1][r];
        int inner = ((r & 7)*4 + (cp & 3))*4 + ((r >> 3) & 1) + 2*((cp >> 2) & 1);
        int local = ((r >> 4) & 1)*256 + ((cp >> 3) & 1)*128 + inner;
        fh[local] = pack2(v0, v1);
        fl[local] = pack2(v0 - bf_round(v0), v1 - bf_round(v1));
    }
    __syncthreads();
    size_t rbg = (size_t)(b * KPTS + k0) >> 4;
    int cg = c0 >> 4;
    #pragma unroll
    for (int rb = 0; rb < 2; rb++) {
        size_t gidx = ((rbg + rb) * 16 + cg) * 128 + t;
        d_fth[gidx] = fh[rb*256 + t];
        d_ftl[gidx] = fl[rb*256 + t];
    }
}

// ---------------- assembly: layer-1 = G(gather) + Wxyz*gxyz, BN, relu -------
__global__ __launch_bounds__(128) void assemble_kernel(const float* __restrict__ xyz,
                                                       const float* __restrict__ G) {
    __shared__ __align__(16) float sW[256*4];
    __shared__ float ss[256], sb2[256];
    __shared__ float cx[4];
    __shared__ int ks[NSAMP];
    int blk = blockIdx.x, b = blk >> 8, tid = threadIdx.x;
    if (tid < NSAMP) ks[tid] = d_idxbuf[blk*NSAMP + tid];
    if (tid < 3)     cx[tid] = d_newxyz[blk*3 + tid];
    for (int i = tid; i < 256; i += 128) {
        *(float4*)&sW[i*4] = *(const float4*)&d_wxyz[i*4];
        ss[i]  = d_sb[i];
        sb2[i] = d_sb[256 + i];
    }
    __syncthreads();
    int c = tid * 2;
    float s0 = ss[c], s1 = ss[c+1], b0 = sb2[c], b1 = sb2[c+1];
    float w00 = sW[c*4], w01 = sW[c*4+1], w02 = sW[c*4+2];
    float w10 = sW[(c+1)*4], w11 = sW[(c+1)*4+1], w12 = sW[(c+1)*4+2];
    for (int s = 0; s < NSAMP; s++) {
        int k = ks[s];
        const float* p = xyz + ((size_t)b * KPTS + k) * 3;
        float gx = (p[0]-cx[0]) / 0.3f;
        float gy = (p[1]-cx[1]) / 0.3f;
        float gz = (p[2]-cx[2]) / 0.3f;
        float2 g = *(const float2*)(G + ((size_t)b * KPTS + k) * 256 + c);
        float v0 = g.x + w00*gx + w01*gy + w02*gz;
        float v1 = g.y + w10*gx + w11*gy + w12*gz;
        v0 = fmaxf(v0 * s0 + b0, 0.f);
        v1 = fmaxf(v1 * s1 + b1, 0.f);
        size_t idx = abf32_off(blk*NSAMP + s, c, 16);
        d_a1h[idx] = pack2(v0, v1);
        d_a1l[idx] = pack2(v0 - bf_round(v0), v1 - bf_round(v1));
    }
}

// ---------------- maxpool: act3 -> Y hi/lo bf16 (frag order) -----------
__global__ __launch_bounds__(256) void maxpool_kernel() {
    int blk = blockIdx.x;
    int c = threadIdx.x;
    const float* src = d_act3 + (size_t)blk * NSAMP * CFEAT;
    float m = src[c];
    #pragma unroll
    for (int s = 1; s < NSAMP; s++) m = fmaxf(m, src[s*CFEAT + c]);
    size_t o2 = abf32_off(blk, c & ~1, 16);
    __nv_bfloat16* yh = (__nv_bfloat16*)d_yh;
    __nv_bfloat16* yl = (__nv_bfloat16*)d_yl;
    size_t o = o2 * 2 + (c & 1);
    yh[o] = __float2bfloat16_rn(m);
    yl[o] = __float2bfloat16_rn(m - bf_round(m));
}

// ---------------- decode head ----------------
__global__ __launch_bounds__(256) void decode_kernel(const float* __restrict__ msa,
                                                     float* __restrict__ out) {
    int g = blockIdx.x * 256 + threadIdx.x;
    if (g >= PROPROW) return;
    const float* nt = d_net + (size_t)g * 128;
    const float* nx = d_newxyz + (size_t)g * 3;

    float obj0 = nt[0], obj1 = nt[1];
    out[OFF_OBJ + 2*g + 0] = obj0;
    out[OFF_OBJ + 2*g + 1] = obj1;

    float cen[3];
    #pragma unroll
    for (int c = 0; c < 3; c++) {
        cen[c] = nx[c] + nt[2 + c];
        out[OFF_CENTER + 3*g + c] = cen[c];
    }

    float bestv = -1e30f; int best = 0;
    #pragma unroll
    for (int j = 0; j < 18; j++) {
        float s = nt[29 + j];
        out[OFF_SSC + 18*g + j] = s;
        if (s > bestv) { bestv = s; best = j; }
    }

    #pragma unroll
    for (int j = 0; j < 18; j++)
        #pragma unroll
        for (int c = 0; c < 3; c++)
            out[OFF_SRES + 54*g + j*3 + c] = nt[47 + j*3 + c] * msa[j*3 + c];

    float ps[3];
    #pragma unroll
    for (int c = 0; c < 3; c++) {
        ps[c] = nt[47 + best*3 + c] * msa[best*3 + c] + msa[best*3 + c];
        out[OFF_PSIZE + 3*g + c] = ps[c];
    }

    float mx = -1e30f;
    #pragma unroll
    for (int j = 0; j < 18; j++) {
        float s = nt[101 + j];
        out[OFF_SEM  + 18*g + j] = s;
        out[OFF_SLOG + 19*g + j] = s;
        mx = fmaxf(mx, s);
    }
    float e[18], sum = 0.0f;
    #pragma unroll
    for (int j = 0; j < 18; j++) { e[j] = expf(nt[101 + j] - mx); sum += e[j]; }
    #pragma unroll
    for (int j = 0; j < 18; j++) out[OFF_SPROB + 18*g + j] = e[j] / sum;

    out[OFF_SLOG + 19*g + 18] = (obj0 <= obj1) ? 0.0f : 1e10f;

    float m2 = fmaxf(obj0, obj1);
    float e0 = expf(obj0 - m2), e1 = expf(obj1 - m2);
    out[OFF_OPROB + g] = e1 / (e0 + e1);

    float cc0 = cen[0], cc1 = cen[2], cc2 = -cen[1];
    const float sxv[8] = {1,1,-1,-1,1,1,-1,-1};
    const float syv[8] = {1,1,1,1,-1,-1,-1,-1};
    const float szv[8] = {1,-1,-1,1,1,-1,-1,1};
    #pragma unroll
    for (int k = 0; k < 8; k++) {
        out[OFF_CORN + 24*g + k*3 + 0] = cc0 + ps[0] * sxv[k] * 0.5f;
        out[OFF_CORN + 24*g + k*3 + 1] = cc1 + ps[2] * syv[k] * 0.5f;
        out[OFF_CORN + 24*g + k*3 + 2] = cc2 + ps[1] * szv[k] * 0.5f;
    }
}

// ---------------- launch ----------------
extern "C" void kernel_launch(void* const* d_in, const int* in_sizes, int n_in,
                              void* d_out, int out_size) {
    const float* xyz      = (const float*)d_in[0];
    const float* features = (const float*)d_in[1];
    const float* sa_w1    = (const float*)d_in[2];
    const float* sa_w2    = (const float*)d_in[3];
    const float* sa_w3    = (const float*)d_in[4];
    const float* sa_gamma = (const float*)d_in[5];
    const float* sa_beta  = (const float*)d_in[6];
    const float* sa_mean  = (const float*)d_in[7];
    const float* sa_var   = (const float*)d_in[8];
    const float* p_w1     = (const float*)d_in[9];
    const float* p_w2     = (const float*)d_in[10];
    const float* p_w3     = (const float*)d_in[11];
    const float* p_b3     = (const float*)d_in[12];
    const float* p_gamma  = (const float*)d_in[13];
    const float* p_beta   = (const float*)d_in[14];
    const float* p_mean   = (const float*)d_in[15];
    const float* p_var    = (const float*)d_in[16];
    const float* msa      = (const float*)d_in[17];
    float* out = (float*)d_out;

    #define GAU(sym) ({ void* _p; cudaGetSymbolAddress(&_p, sym); (uint32_t*)_p; })
    #define GAF(sym) ({ void* _p; cudaGetSymbolAddress(&_p, sym); (float*)_p; })
    uint32_t* FTH = GAU(d_fth); uint32_t* FTL = GAU(d_ftl);
    uint32_t* A1H = GAU(d_a1h); uint32_t* A1L = GAU(d_a1l);
    uint32_t* A2H = GAU(d_a2h); uint32_t* A2L = GAU(d_a2l);
    float* A3  = GAF(d_act3);
    uint32_t* YH  = GAU(d_yh);  uint32_t* YL  = GAU(d_yl);
    uint32_t* P1H = GAU(d_p1h); uint32_t* P1L = GAU(d_p1l);
    uint32_t* P2H = GAU(d_p2h); uint32_t* P2L = GAU(d_p2l);
    float* NET = GAF(d_net);
    float* SB  = GAF(d_sb);  float* ONE = GAF(d_one);
    float* ZERO = GAF(d_zero); float* B3P = GAF(d_b3p);
    uint32_t* W1H = GAU(d_w1ph); uint32_t* W1L = GAU(d_w1pl);
    uint32_t* W2H = GAU(d_w2ph); uint32_t* W2L = GAU(d_w2pl);
    uint32_t* W3H = GAU(d_w3ph); uint32_t* W3L = GAU(d_w3pl);
    uint32_t* Q1H = GAU(d_pw1h); uint32_t* Q1L = GAU(d_pw1l);
    uint32_t* Q2H = GAU(d_pw2h); uint32_t* Q2L = GAU(d_pw2l);
    uint32_t* HWH = GAU(d_hwh);  uint32_t* HWL = GAU(d_hwl);
    #undef GAU
    #undef GAF

    cudaFuncSetAttribute(gemm_mma, cudaFuncAttributeMaxDynamicSharedMemorySize, GEMM_SMEM);

    // W1 feature part: cols 3..258 of sa_w1 (row stride 259)
    permW_kernel<<<2*8*8, 256>>>(sa_w1, 256, 259, 3, 256, W1H, W1L);
    permW_kernel<<<2*8*8, 256>>>(sa_w2, 256, 256, 0, 256, W2H, W2L);
    permW_kernel<<<2*8*8, 256>>>(sa_w3, 256, 256, 0, 256, W3H, W3L);
    permW_kernel<<<2*8*8, 256>>>(p_w1, 256, 256, 0, 256, Q1H, Q1L);
    permW_kernel<<<2*8*8, 256>>>(p_w2, 256, 256, 0, 256, Q2H, Q2L);
    permW_kernel<<<1*8*8, 256>>>(p_w3, OUTD, 256, 0, 256, HWH, HWL);
    sb_kernel<<<7, 256>>>(sa_gamma, sa_beta, sa_mean, sa_var,
                          p_gamma, p_beta, p_mean, p_var, p_b3, sa_w1);
    fps_kernel<<<BB, 256>>>(xyz);
    bq_kernel<<<PROPROW/8, 256>>>(xyz);
    transfrag_kernel<<<dim3(KPTS/32, CFEAT/32, BB), dim3(32, 8)>>>(features);

    // per-point feature GEMM: G = W1_feat . feat  (65536 x 256), plain fp32 out
    gemm_mma<<<PTROW/128*2, 256, GEMM_SMEM>>>(FTH, FTL, 16, W1H, W1L,
        A3, (uint32_t*)0, (uint32_t*)0, 256, 8, ONE, ZERO, 1, 1);

    // layer-1 assembly: gather G + xyz matvec + BN/relu -> a1 frags
    assemble_kernel<<<PROPROW, 128>>>(xyz, A3);

    // SA layers 2,3
    gemm_mma<<<TOTROW/128*2, 256, GEMM_SMEM>>>(A1H, A1L, 16, W2H, W2L,
        (float*)0, A2H, A2L, 256, 8, SB + 1*512, SB + 1*512 + 256, 0, 1);
    gemm_mma<<<TOTROW/128*2, 256, GEMM_SMEM>>>(A2H, A2L, 16, W3H, W3L,
        A3, (uint32_t*)0, (uint32_t*)0, 256, 8, SB + 2*512, SB + 2*512 + 256, 0, 1);

    maxpool_kernel<<<PROPROW, 256>>>();

    // proposal layers
    gemm_mma<<<PROPROW/128*2, 256, GEMM_SMEM>>>(YH, YL, 16, Q1H, Q1L,
        (float*)0, P1H, P1L, 256, 8, SB + 3*512, SB + 3*512 + 256, 0, 1);
    gemm_mma<<<PROPROW/128*2, 256, GEMM_SMEM>>>(P1H, P1L, 16, Q2H, Q2L,
        (float*)0, P2H, P2L, 256, 8, SB + 4*512, SB + 4*512 + 256, 0, 1);
    gemm_mma<<<PROPROW/128, 256, GEMM_SMEM>>>(P2H, P2L, 16, HWH, HWL,
        NET, (uint32_t*)0, (uint32_t*)0, 128, 8, ONE, B3P, 1, 0);

    decode_kernel<<<PROPROW/256, 256>>>(msa, out);
}

// round 15
// speedup vs baseline: 1.9166x; 1.0463x over previous
#include <cuda_runtime.h>
#include <cuda_bf16.h>
#include <math.h>
#include <stdint.h>

#define BB 32
#define KPTS 2048
#define CFEAT 256
#define NPROP 256
#define NSAMP 16
#define OUTD 119
#define TOTROW (BB*16*NPROP)   // 131072
#define PTROW  (BB*KPTS)       // 65536
#define PROPROW (BB*NPROP)     // 8192

#define BSTU 4096
#define GEMM_SMEM ((2*BSTU + 256) * 4)   // 34816 bytes

// ---------------- scratch ----------------
__device__ uint32_t d_fth[(size_t)PTROW*CFEAT/2];
__device__ uint32_t d_ftl[(size_t)PTROW*CFEAT/2];
__device__ uint32_t d_a1h[(size_t)TOTROW*CFEAT/2];
__device__ uint32_t d_a1l[(size_t)TOTROW*CFEAT/2];
__device__ uint32_t d_a2h[(size_t)TOTROW*CFEAT/2];
__device__ uint32_t d_a2l[(size_t)TOTROW*CFEAT/2];
__device__ float d_G[(size_t)PTROW*CFEAT];          // per-point W1*feat
__device__ uint32_t d_yh [(size_t)PROPROW*CFEAT/2];
__device__ uint32_t d_yl [(size_t)PROPROW*CFEAT/2];
__device__ uint32_t d_p1h[(size_t)PROPROW*CFEAT/2];
__device__ uint32_t d_p1l[(size_t)PROPROW*CFEAT/2];
__device__ uint32_t d_p2h[(size_t)PROPROW*CFEAT/2];
__device__ uint32_t d_p2l[(size_t)PROPROW*CFEAT/2];
__device__ float d_net[(size_t)PROPROW*128];
__device__ float d_newxyz[PROPROW*3];
__device__ int   d_idxbuf[PROPROW*NSAMP];
__device__ float d_sb[5*2*256];
__device__ float d_one[256];
__device__ float d_zero[256];
__device__ float d_b3p[128];
__device__ float d_wxyz[256*4];
__device__ uint32_t d_w1ph[2*8*2048],  d_w1pl[2*8*2048];
__device__ uint32_t d_w2ph[2*8*2048],  d_w2pl[2*8*2048];
__device__ uint32_t d_w3ph[2*8*2048],  d_w3pl[2*8*2048];
__device__ uint32_t d_pw1h[2*8*2048],  d_pw1l[2*8*2048];
__device__ uint32_t d_pw2h[2*8*2048],  d_pw2l[2*8*2048];
__device__ uint32_t d_hwh [1*8*2048],  d_hwl [1*8*2048];

// ---------------- output layout offsets ----------------
#define OFF_OBJ    0LL
#define OFF_CENTER 16384LL
#define OFF_SSC    40960LL
#define OFF_SRES   188416LL
#define OFF_PSIZE  630784LL
#define OFF_SEM    655360LL
#define OFF_CORN   802816LL
#define OFF_SLOG   999424LL
#define OFF_OPROB  1155072LL
#define OFF_SPROB  1163264LL

__device__ __forceinline__ uint32_t smem_u32(const void* p) {
    uint32_t a;
    asm("{ .reg .u64 t; cvta.to.shared.u64 t, %1; cvt.u32.u64 %0, t; }" : "=r"(a) : "l"(p));
    return a;
}
__device__ __forceinline__ void cp16(uint32_t s, const void* g) {
    asm volatile("cp.async.cg.shared.global [%0], [%1], 16;" :: "r"(s), "l"(g));
}
#define CP_COMMIT() asm volatile("cp.async.commit_group;" ::: "memory")
#define CP_WAIT1()  asm volatile("cp.async.wait_group 1;" ::: "memory")
#define CP_WAIT0()  asm volatile("cp.async.wait_group 0;" ::: "memory")

__device__ __forceinline__ void mma_bf16(float* c, const uint32_t* a,
                                         uint32_t b0, uint32_t b1) {
    asm volatile(
        "mma.sync.aligned.m16n8k16.row.col.f32.bf16.bf16.f32 "
        "{%0,%1,%2,%3}, {%4,%5,%6,%7}, {%8,%9}, {%0,%1,%2,%3};"
        : "+f"(c[0]), "+f"(c[1]), "+f"(c[2]), "+f"(c[3])
        : "r"(a[0]), "r"(a[1]), "r"(a[2]), "r"(a[3]), "r"(b0), "r"(b1));
}

// uint32 index for A-frag pair (c even)
__device__ __forceinline__ size_t abf32_off(int row, int c, int nk16) {
    return ((size_t)(row >> 4) * nk16 + (c >> 4)) * 128
         + (size_t)((row & 7) * 4 + ((c >> 1) & 3)) * 4
         + ((row >> 3) & 1) + 2 * ((c >> 3) & 1);
}

__device__ __forceinline__ uint32_t pack2(float x, float y) {
    unsigned short lo = __bfloat16_as_ushort(__float2bfloat16_rn(x));
    unsigned short hi = __bfloat16_as_ushort(__float2bfloat16_rn(y));
    return (uint32_t)lo | ((uint32_t)hi << 16);
}
__device__ __forceinline__ float bf_round(float x) {
    return __bfloat162float(__float2bfloat16_rn(x));
}

// ============ 3xBF16 GEMM: B smem double-buffered, A direct LDG ============
// mode 0: relu(v*s+b) -> hi/lo frags (Ch/Cl) or f32 (Cf)
// mode 1: v + b        -> f32 (Cf)
// mode 2: relu(v*s+b), max over each 16-row proposal -> Y hi/lo frags
__global__ __launch_bounds__(256, 2) void gemm_mma(
    const uint32_t* __restrict__ Ah, const uint32_t* __restrict__ Al, int nk16A,
    const uint32_t* __restrict__ Bph, const uint32_t* __restrict__ Bpl,
    float* __restrict__ Cf, uint32_t* __restrict__ Ch, uint32_t* __restrict__ Cl,
    int ldc, int nchunk,
    const float* __restrict__ scale, const float* __restrict__ bias,
    int mode, int nybm1)
{
    extern __shared__ uint32_t smu[];
    float* s_s = (float*)(smu + 2*BSTU);
    float* s_b = s_s + 128;
    const uint32_t smb = smem_u32(smu);

    const int tid = threadIdx.x;
    const int lane = tid & 31, wid = tid >> 5;
    const int wm = wid & 3, wn = wid >> 2;
    const int yb = blockIdx.x & nybm1;
    const long long xb = blockIdx.x >> nybm1;
    const long long m0 = xb * 128;
    const int y0 = yb * 128;
    const int lq = lane >> 2, lr = lane & 3;

    if (tid < 128) {
        s_s[tid] = (mode != 1) ? scale[y0 + tid] : 1.0f;
        s_b[tid] = bias[y0 + tid];
    }

    float acc[2][8][4];
    #pragma unroll
    for (int mt = 0; mt < 2; mt++)
        #pragma unroll
        for (int nt = 0; nt < 8; nt++)
            #pragma unroll
            for (int j = 0; j < 4; j++) acc[mt][nt][j] = 0.0f;

    const size_t rbase0 = (size_t)(xb * 8 + wm * 2 + 0) * nk16A * 128 + lane * 4;
    const size_t rbase1 = rbase0 + (size_t)nk16A * 128;

    const size_t bbase = (size_t)yb * nchunk * 2048;

    auto stageB = [&](int kc) {
        const uint32_t sb0 = smb + (kc & 1) * BSTU * 4;
        const size_t bg = bbase + (size_t)kc * 2048;
        #pragma unroll
        for (int it = 0; it < 2; it++) {
            int idx = tid + it * 256;
            cp16(sb0 + (uint32_t)idx * 16, Bph + bg + idx * 4);
            cp16(sb0 + 2048*4 + (uint32_t)idx * 16, Bpl + bg + idx * 4);
        }
    };

    stageB(0); CP_COMMIT();

    for (int kc = 0; kc < nchunk; kc++) {
        if (kc + 1 < nchunk) { stageB(kc + 1); CP_COMMIT(); CP_WAIT1(); }
        else CP_WAIT0();
        __syncthreads();

        const uint32_t* sBh = smu + (kc & 1) * BSTU;
        const uint32_t* sBl = sBh + 2048;

        #pragma unroll
        for (int k16l = 0; k16l < 2; k16l++) {
            const size_t ao = (size_t)(kc * 2 + k16l) * 128;
            uint4 ah0 = *(const uint4*)(Ah + rbase0 + ao);
            uint4 ah1 = *(const uint4*)(Ah + rbase1 + ao);
            uint4 al0 = *(const uint4*)(Al + rbase0 + ao);
            uint4 al1 = *(const uint4*)(Al + rbase1 + ao);
            uint2 bh[8], bl[8];
            #pragma unroll
            for (int nt = 0; nt < 8; nt++) {
                int fo = (k16l*16 + wn*8 + nt)*64 + lane*2;
                bh[nt] = *(const uint2*)(sBh + fo);
                bl[nt] = *(const uint2*)(sBl + fo);
            }
            #pragma unroll
            for (int nt = 0; nt < 8; nt++) {
                mma_bf16(acc[0][nt], (const uint32_t*)&al0, bh[nt].x, bh[nt].y);
                mma_bf16(acc[1][nt], (const uint32_t*)&al1, bh[nt].x, bh[nt].y);
            }
            #pragma unroll
            for (int nt = 0; nt < 8; nt++) {
                mma_bf16(acc[0][nt], (const uint32_t*)&ah0, bl[nt].x, bl[nt].y);
                mma_bf16(acc[1][nt], (const uint32_t*)&ah1, bl[nt].x, bl[nt].y);
            }
            #pragma unroll
            for (int nt = 0; nt < 8; nt++) {
                mma_bf16(acc[0][nt], (const uint32_t*)&ah0, bh[nt].x, bh[nt].y);
                mma_bf16(acc[1][nt], (const uint32_t*)&ah1, bh[nt].x, bh[nt].y);
            }
        }
        __syncthreads();
    }

    const int nk16o = ldc >> 4;
    #pragma unroll
    for (int mt = 0; mt < 2; mt++) {
        long long r0 = m0 + wm * 32 + mt * 16 + lq;
        size_t rb = (size_t)(m0 + wm * 32 + mt * 16) >> 4;
        #pragma unroll
        for (int nt = 0; nt < 8; nt++) {
            int gc = wn * 64 + nt * 8 + 2 * lr;
            float s0 = s_s[gc], s1 = s_s[gc + 1];
            float b0 = s_b[gc], b1 = s_b[gc + 1];
            float v00 = acc[mt][nt][0] * s0 + b0;
            float v01 = acc[mt][nt][1] * s1 + b1;
            float v10 = acc[mt][nt][2] * s0 + b0;
            float v11 = acc[mt][nt][3] * s1 + b1;
            if (mode != 1) {
                v00 = fmaxf(v00, 0.f); v01 = fmaxf(v01, 0.f);
                v10 = fmaxf(v10, 0.f); v11 = fmaxf(v11, 0.f);
            }
            if (mode == 2) {
                // max over the 16-row proposal: pair rows, then lq lanes
                float m0v = fmaxf(v00, v10);
                float m1v = fmaxf(v01, v11);
                #pragma unroll
                for (int off = 4; off <= 16; off <<= 1) {
                    m0v = fmaxf(m0v, __shfl_xor_sync(0xffffffffu, m0v, off));
                    m1v = fmaxf(m1v, __shfl_xor_sync(0xffffffffu, m1v, off));
                }
                if (lq == 0) {
                    int prop = (int)((m0 + wm * 32 + mt * 16) >> 4);
                    size_t idx = abf32_off(prop, y0 + gc, 16);
                    Ch[idx] = pack2(m0v, m1v);
                    Cl[idx] = pack2(m0v - bf_round(m0v), m1v - bf_round(m1v));
                }
            } else if (Ch) {
                size_t blk = (rb * nk16o + (y0 >> 4) + wn * 4 + (nt >> 1)) * 128
                           + (size_t)(lq * 4 + lr) * 4 + 2 * (nt & 1);
                Ch[blk]     = pack2(v00, v01);
                Ch[blk + 1] = pack2(v10, v11);
                Cl[blk]     = pack2(v00 - bf_round(v00), v01 - bf_round(v01));
                Cl[blk + 1] = pack2(v10 - bf_round(v10), v11 - bf_round(v11));
            } else {
                *(float2*)(Cf + r0 * ldc + y0 + gc)       = make_float2(v00, v01);
                *(float2*)(Cf + (r0 + 8) * ldc + y0 + gc) = make_float2(v10, v11);
            }
        }
    }
}

// ---------------- all weight permutes in one kernel ----------------
__global__ void permAll_kernel(const float* __restrict__ w1, const float* __restrict__ w2,
                               const float* __restrict__ w3, const float* __restrict__ q1,
                               const float* __restrict__ q2, const float* __restrict__ hw) {
    int blk = blockIdx.x;
    const float* W; uint32_t *oh, *ol; int nrows, ld, koff, base;
    if (blk < 128)      { W=w1; oh=d_w1ph; ol=d_w1pl; nrows=256;  ld=259; koff=3; base=0; }
    else if (blk < 256) { W=w2; oh=d_w2ph; ol=d_w2pl; nrows=256;  ld=256; koff=0; base=128; }
    else if (blk < 384) { W=w3; oh=d_w3ph; ol=d_w3pl; nrows=256;  ld=256; koff=0; base=256; }
    else if (blk < 512) { W=q1; oh=d_pw1h; ol=d_pw1l; nrows=256;  ld=256; koff=0; base=384; }
    else if (blk < 640) { W=q2; oh=d_pw2h; ol=d_pw2l; nrows=256;  ld=256; koff=0; base=512; }
    else                { W=hw; oh=d_hwh;  ol=d_hwl;  nrows=OUTD; ld=256; koff=0; base=640; }
    int e = (blk - base) * 256 + threadIdx.x;
    int yb = e / (8 * 2048);
    int rem = e - yb * 8 * 2048;
    int kc = rem >> 11;
    int w = rem & 2047;
    int k16l = w >> 10, ntile = (w >> 6) & 15, lane = (w >> 1) & 31, breg = w & 1;
    int o = yb * 128 + ntile * 8 + (lane >> 2);
    int k = kc * 32 + k16l * 16 + breg * 8 + (lane & 3) * 2;
    float v0 = (o < nrows) ? W[o * ld + koff + k]     : 0.0f;
    float v1 = (o < nrows) ? W[o * ld + koff + k + 1] : 0.0f;
    oh[e] = pack2(v0, v1);
    ol[e] = pack2(v0 - bf_round(v0), v1 - bf_round(v1));
}

__global__ void sb_kernel(const float* __restrict__ sg, const float* __restrict__ sbe,
                          const float* __restrict__ sm, const float* __restrict__ sv,
                          const float* __restrict__ pg, const float* __restrict__ pb,
                          const float* __restrict__ pm, const float* __restrict__ pv,
                          const float* __restrict__ b3, const float* __restrict__ w1) {
    int l = blockIdx.x, t = threadIdx.x;
    if (l == 5) {
        if (t < 128) d_b3p[t] = (t < OUTD) ? b3[t] : 0.0f;
        d_one[t] = 1.0f;
        d_zero[t] = 0.0f;
        return;
    }
    if (l == 6) {
        d_wxyz[t*4+0] = w1[t*259+0];
        d_wxyz[t*4+1] = w1[t*259+1];
        d_wxyz[t*4+2] = w1[t*259+2];
        d_wxyz[t*4+3] = 0.0f;
        return;
    }
    float g, bt, m, v;
    if (l < 3) { g = sg[l*256+t]; bt = sbe[l*256+t]; m = sm[l*256+t]; v = sv[l*256+t]; }
    else { int q = l - 3; g = pg[q*256+t]; bt = pb[q*256+t]; m = pm[q*256+t]; v = pv[q*256+t]; }
    float s = g / sqrtf(v + 1e-5f);
    d_sb[l*512 + t] = s;
    d_sb[l*512 + 256 + t] = bt - m * s;
}

// ---------------- FPS (single barrier per iteration) ----------------
__global__ __launch_bounds__(256) void fps_kernel(const float* __restrict__ xyz) {
    __shared__ float sx[KPTS], sy[KPTS], sz[KPTS];
    __shared__ unsigned long long skey[2][8];
    int b = blockIdx.x, tid = threadIdx.x;
    const float* base = xyz + (size_t)b * KPTS * 3;
    for (int k = tid; k < KPTS; k += 256) {
        sx[k] = base[k*3+0]; sy[k] = base[k*3+1]; sz[k] = base[k*3+2];
    }
    float dreg[8];
    #pragma unroll
    for (int j = 0; j < 8; j++) dreg[j] = 1e10f;
    int far = 0;
    int warp = tid >> 5, lane = tid & 31;
    __syncthreads();
    for (int i = 0; i < NPROP; i++) {
        float cx = sx[far], cy = sy[far], cz = sz[far];
        if (tid == 0) {
            d_newxyz[(b*NPROP+i)*3+0] = cx;
            d_newxyz[(b*NPROP+i)*3+1] = cy;
            d_newxyz[(b*NPROP+i)*3+2] = cz;
        }
        float bv = -1.0f; int bi = 0x7fffffff;
        #pragma unroll
        for (int j = 0; j < 8; j++) {
            int k = tid + j * 256;
            float dx = sx[k]-cx, dy = sy[k]-cy, dz = sz[k]-cz;
            float d = __fadd_rn(__fadd_rn(__fmul_rn(dx,dx), __fmul_rn(dy,dy)), __fmul_rn(dz,dz));
            dreg[j] = fminf(dreg[j], d);
            if (dreg[j] > bv) { bv = dreg[j]; bi = k; }
        }
        unsigned bvb = __float_as_uint(bv);
        unsigned vmax = __reduce_max_sync(0xffffffffu, bvb);
        unsigned cand = (bvb == vmax) ? (unsigned)bi : 0x7fffffffu;
        unsigned bidx = __reduce_min_sync(0xffffffffu, cand);
        if (lane == 0)
            skey[i & 1][warp] = ((unsigned long long)vmax << 32)
                              | (unsigned)(0x7fffffffu - bidx);
        __syncthreads();
        unsigned long long best = 0;
        #pragma unroll
        for (int w = 0; w < 8; w++) {
            unsigned long long kk = skey[i & 1][w];
            if (kk > best) best = kk;
        }
        far = (int)(0x7fffffffu - (unsigned)(best & 0xffffffffu));
    }
}

// ---------------- ball query: one warp per proposal ----------------
__global__ __launch_bounds__(256) void bq_kernel(const float* __restrict__ xyz) {
    int w = threadIdx.x >> 5, lane = threadIdx.x & 31;
    int p = blockIdx.x * 8 + w;
    int b = p >> 8;
    const float* base = xyz + (size_t)b * KPTS * 3;
    float nx = d_newxyz[p*3+0];
    float ny = d_newxyz[p*3+1];
    float nz = d_newxyz[p*3+2];
    int* dst = d_idxbuf + p * NSAMP;
    int cnt = 0, first = 0;
    const float R2 = 0.09f;
    for (int ch = 0; ch < KPTS/32; ch++) {
        int k = ch * 32 + lane;
        float dx = base[k*3+0]-nx, dy = base[k*3+1]-ny, dz = base[k*3+2]-nz;
        float d = __fadd_rn(__fadd_rn(__fmul_rn(dx,dx), __fmul_rn(dy,dy)), __fmul_rn(dz,dz));
        bool in = d < R2;
        unsigned mask = __ballot_sync(0xffffffffu, in);
        if (cnt == 0 && mask) first = ch * 32 + __ffs(mask) - 1;
        if (in) {
            int slot = cnt + __popc(mask & ((1u << lane) - 1u));
            if (slot < NSAMP) dst[slot] = k;
        }
        cnt += __popc(mask);
        if (cnt >= NSAMP) break;
    }
    if (cnt < NSAMP && lane >= cnt && lane < NSAMP) dst[lane] = first;
}

// ---------------- transpose features -> bf16 hi/lo frags ----------------
__global__ void transfrag_kernel(const float* __restrict__ in) {
    __shared__ float tile[32][33];
    __shared__ uint32_t fh[512], fl[512];
    int b = blockIdx.z;
    int k0 = blockIdx.x * 32, c0 = blockIdx.y * 32;
    const float* src = in + (size_t)b * CFEAT * KPTS;
    int tx = threadIdx.x, ty = threadIdx.y;
    #pragma unroll
    for (int i = 0; i < 4; i++)
        tile[ty + i*8][tx] = src[(size_t)(c0 + ty + i*8) * KPTS + k0 + tx];
    __syncthreads();
    int t = ty * 32 + tx;
    #pragma unroll
    for (int uu = 0; uu < 2; uu++) {
        int u = t + uu * 256;
        int r = u & 31, cp = u >> 5;
        float v0 = tile[cp*2][r], v1 = tile[cp*2+1][r];
        int inner = ((r & 7)*4 + (cp & 3))*4 + ((r >> 3) & 1) + 2*((cp >> 2) & 1);
        int local = ((r >> 4) & 1)*256 + ((cp >> 3) & 1)*128 + inner;
        fh[local] = pack2(v0, v1);
        fl[local] = pack2(v0 - bf_round(v0), v1 - bf_round(v1));
    }
    __syncthreads();
    size_t rbg = (size_t)(b * KPTS + k0) >> 4;
    int cg = c0 >> 4;
    #pragma unroll
    for (int rb = 0; rb < 2; rb++) {
        size_t gidx = ((rbg + rb) * 16 + cg) * 128 + t;
        d_fth[gidx] = fh[rb*256 + t];
        d_ftl[gidx] = fl[rb*256 + t];
    }
}

// ---------------- assembly: layer-1 = G(gather) + Wxyz*gxyz, BN, relu -------
__global__ __launch_bounds__(128) void assemble_kernel(const float* __restrict__ xyz,
                                                       const float* __restrict__ G) {
    __shared__ __align__(16) float sW[256*4];
    __shared__ float ss[256], sb2[256];
    __shared__ float cx[4];
    __shared__ int ks[NSAMP];
    int blk = blockIdx.x, b = blk >> 8, tid = threadIdx.x;
    if (tid < NSAMP) ks[tid] = d_idxbuf[blk*NSAMP + tid];
    if (tid < 3)     cx[tid] = d_newxyz[blk*3 + tid];
    for (int i = tid; i < 256; i += 128) {
        *(float4*)&sW[i*4] = *(const float4*)&d_wxyz[i*4];
        ss[i]  = d_sb[i];
        sb2[i] = d_sb[256 + i];
    }
    __syncthreads();
    int c = tid * 2;
    float s0 = ss[c], s1 = ss[c+1], b0 = sb2[c], b1 = sb2[c+1];
    float w00 = sW[c*4], w01 = sW[c*4+1], w02 = sW[c*4+2];
    float w10 = sW[(c+1)*4], w11 = sW[(c+1)*4+1], w12 = sW[(c+1)*4+2];
    for (int s = 0; s < NSAMP; s++) {
        int k = ks[s];
        const float* p = xyz + ((size_t)b * KPTS + k) * 3;
        float gx = (p[0]-cx[0]) / 0.3f;
        float gy = (p[1]-cx[1]) / 0.3f;
        float gz = (p[2]-cx[2]) / 0.3f;
        float2 g = *(const float2*)(G + ((size_t)b * KPTS + k) * 256 + c);
        float v0 = g.x + w00*gx + w01*gy + w02*gz;
        float v1 = g.y + w10*gx + w11*gy + w12*gz;
        v0 = fmaxf(v0 * s0 + b0, 0.f);
        v1 = fmaxf(v1 * s1 + b1, 0.f);
        size_t idx = abf32_off(blk*NSAMP + s, c, 16);
        d_a1h[idx] = pack2(v0, v1);
        d_a1l[idx] = pack2(v0 - bf_round(v0), v1 - bf_round(v1));
    }
}

// ---------------- decode head ----------------
__global__ __launch_bounds__(256) void decode_kernel(const float* __restrict__ msa,
                                                     float* __restrict__ out) {
    int g = blockIdx.x * 256 + threadIdx.x;
    if (g >= PROPROW) return;
    const float* nt = d_net + (size_t)g * 128;
    const float* nx = d_newxyz + (size_t)g * 3;

    float obj0 = nt[0], obj1 = nt[1];
    out[OFF_OBJ + 2*g + 0] = obj0;
    out[OFF_OBJ + 2*g + 1] = obj1;

    float cen[3];
    #pragma unroll
    for (int c = 0; c < 3; c++) {
        cen[c] = nx[c] + nt[2 + c];
        out[OFF_CENTER + 3*g + c] = cen[c];
    }

    float bestv = -1e30f; int best = 0;
    #pragma unroll
    for (int j = 0; j < 18; j++) {
        float s = nt[29 + j];
        out[OFF_SSC + 18*g + j] = s;
        if (s > bestv) { bestv = s; best = j; }
    }

    #pragma unroll
    for (int j = 0; j < 18; j++)
        #pragma unroll
        for (int c = 0; c < 3; c++)
            out[OFF_SRES + 54*g + j*3 + c] = nt[47 + j*3 + c] * msa[j*3 + c];

    float ps[3];
    #pragma unroll
    for (int c = 0; c < 3; c++) {
        ps[c] = nt[47 + best*3 + c] * msa[best*3 + c] + msa[best*3 + c];
        out[OFF_PSIZE + 3*g + c] = ps[c];
    }

    float mx = -1e30f;
    #pragma unroll
    for (int j = 0; j < 18; j++) {
        float s = nt[101 + j];
        out[OFF_SEM  + 18*g + j] = s;
        out[OFF_SLOG + 19*g + j] = s;
        mx = fmaxf(mx, s);
    }
    float e[18], sum = 0.0f;
    #pragma unroll
    for (int j = 0; j < 18; j++) { e[j] = expf(nt[101 + j] - mx); sum += e[j]; }
    #pragma unroll
    for (int j = 0; j < 18; j++) out[OFF_SPROB + 18*g + j] = e[j] / sum;

    out[OFF_SLOG + 19*g + 18] = (obj0 <= obj1) ? 0.0f : 1e10f;

    float m2 = fmaxf(obj0, obj1);
    float e0 = expf(obj0 - m2), e1 = expf(obj1 - m2);
    out[OFF_OPROB + g] = e1 / (e0 + e1);

    float cc0 = cen[0], cc1 = cen[2], cc2 = -cen[1];
    const float sxv[8] = {1,1,-1,-1,1,1,-1,-1};
    const float syv[8] = {1,1,1,1,-1,-1,-1,-1};
    const float szv[8] = {1,-1,-1,1,1,-1,-1,1};
    #pragma unroll
    for (int k = 0; k < 8; k++) {
        out[OFF_CORN + 24*g + k*3 + 0] = cc0 + ps[0] * sxv[k] * 0.5f;
        out[OFF_CORN + 24*g + k*3 + 1] = cc1 + ps[2] * syv[k] * 0.5f;
        out[OFF_CORN + 24*g + k*3 + 2] = cc2 + ps[1] * szv[k] * 0.5f;
    }
}

// ---------------- launch ----------------
extern "C" void kernel_launch(void* const* d_in, const int* in_sizes, int n_in,
                              void* d_out, int out_size) {
    const float* xyz      = (const float*)d_in[0];
    const float* features = (const float*)d_in[1];
    const float* sa_w1    = (const float*)d_in[2];
    const float* sa_w2    = (const float*)d_in[3];
    const float* sa_w3    = (const float*)d_in[4];
    const float* sa_gamma = (const float*)d_in[5];
    const float* sa_beta  = (const float*)d_in[6];
    const float* sa_mean  = (const float*)d_in[7];
    const float* sa_var   = (const float*)d_in[8];
    const float* p_w1     = (const float*)d_in[9];
    const float* p_w2     = (const float*)d_in[10];
    const float* p_w3     = (const float*)d_in[11];
    const float* p_b3     = (const float*)d_in[12];
    const float* p_gamma  = (const float*)d_in[13];
    const float* p_beta   = (const float*)d_in[14];
    const float* p_mean   = (const float*)d_in[15];
    const float* p_var    = (const float*)d_in[16];
    const float* msa      = (const float*)d_in[17];
    float* out = (float*)d_out;

    #define GAU(sym) ({ void* _p; cudaGetSymbolAddress(&_p, sym); (uint32_t*)_p; })
    #define GAF(sym) ({ void* _p; cudaGetSymbolAddress(&_p, sym); (float*)_p; })
    uint32_t* FTH = GAU(d_fth); uint32_t* FTL = GAU(d_ftl);
    uint32_t* A1H = GAU(d_a1h); uint32_t* A1L = GAU(d_a1l);
    uint32_t* A2H = GAU(d_a2h); uint32_t* A2L = GAU(d_a2l);
    float* G   = GAF(d_G);
    uint32_t* YH  = GAU(d_yh);  uint32_t* YL  = GAU(d_yl);
    uint32_t* P1H = GAU(d_p1h); uint32_t* P1L = GAU(d_p1l);
    uint32_t* P2H = GAU(d_p2h); uint32_t* P2L = GAU(d_p2l);
    float* NET = GAF(d_net);
    float* SB  = GAF(d_sb);  float* ONE = GAF(d_one);
    float* ZERO = GAF(d_zero); float* B3P = GAF(d_b3p);
    uint32_t* W1H = GAU(d_w1ph); uint32_t* W1L = GAU(d_w1pl);
    uint32_t* W2H = GAU(d_w2ph); uint32_t* W2L = GAU(d_w2pl);
    uint32_t* W3H = GAU(d_w3ph); uint32_t* W3L = GAU(d_w3pl);
    uint32_t* Q1H = GAU(d_pw1h); uint32_t* Q1L = GAU(d_pw1l);
    uint32_t* Q2H = GAU(d_pw2h); uint32_t* Q2L = GAU(d_pw2l);
    uint32_t* HWH = GAU(d_hwh);  uint32_t* HWL = GAU(d_hwl);
    #undef GAU
    #undef GAF

    cudaFuncSetAttribute(gemm_mma, cudaFuncAttributeMaxDynamicSharedMemorySize, GEMM_SMEM);

    permAll_kernel<<<704, 256>>>(sa_w1, sa_w2, sa_w3, p_w1, p_w2, p_w3);
    sb_kernel<<<7, 256>>>(sa_gamma, sa_beta, sa_mean, sa_var,
                          p_gamma, p_beta, p_mean, p_var, p_b3, sa_w1);
    fps_kernel<<<BB, 256>>>(xyz);
    bq_kernel<<<PROPROW/8, 256>>>(xyz);
    transfrag_kernel<<<dim3(KPTS/32, CFEAT/32, BB), dim3(32, 8)>>>(features);

    // per-point feature GEMM: G = W1_feat . feat  (65536 x 256), fp32 out
    gemm_mma<<<PTROW/128*2, 256, GEMM_SMEM>>>(FTH, FTL, 16, W1H, W1L,
        G, (uint32_t*)0, (uint32_t*)0, 256, 8, ONE, ZERO, 1, 1);

    // layer-1 assembly: gather G + xyz matvec + BN/relu -> a1 frags
    assemble_kernel<<<PROPROW, 128>>>(xyz, G);

    // SA layer 2
    gemm_mma<<<TOTROW/128*2, 256, GEMM_SMEM>>>(A1H, A1L, 16, W2H, W2L,
        (float*)0, A2H, A2L, 256, 8, SB + 1*512, SB + 1*512 + 256, 0, 1);
    // SA layer 3 fused with maxpool -> Y frags
    gemm_mma<<<TOTROW/128*2, 256, GEMM_SMEM>>>(A2H, A2L, 16, W3H, W3L,
        (float*)0, YH, YL, 256, 8, SB + 2*512, SB + 2*512 + 256, 2, 1);

    // proposal layers
    gemm_mma<<<PROPROW/128*2, 256, GEMM_SMEM>>>(YH, YL, 16, Q1H, Q1L,
        (float*)0, P1H, P1L, 256, 8, SB + 3*512, SB + 3*512 + 256, 0, 1);
    gemm_mma<<<PROPROW/128*2, 256, GEMM_SMEM>>>(P1H, P1L, 16, Q2H, Q2L,
        (float*)0, P2H, P2L, 256, 8, SB + 4*512, SB + 4*512 + 256, 0, 1);
    gemm_mma<<<PROPROW/128, 256, GEMM_SMEM>>>(P2H, P2L, 16, HWH, HWL,
        NET, (uint32_t*)0, (uint32_t*)0, 128, 8, ONE, B3P, 1, 0);

    decode_kernel<<<PROPROW/256, 256>>>(msa, out);
}